// round 12
// baseline (speedup 1.0000x reference)
#include <cuda_runtime.h>
#include <cuda_bf16.h>
#include <cuda_fp16.h>
#include <cstdint>
#include <math.h>

// ---------------- problem constants ----------------
#define B   8
#define T   4096
#define D_IN 256
#define D   512
#define LQ  256
#define H   8
#define HD  64
#define NB  6
#define HID 2048
#define KVN (NB * 2 * D)

// ---------------- helpers ----------------
__device__ __forceinline__ uint32_t smem_u32(const void* p) {
    uint32_t a;
    asm("{ .reg .u64 t; cvta.to.shared.u64 t, %1; cvt.u32.u64 %0, t; }" : "=r"(a) : "l"(p));
    return a;
}
__device__ __forceinline__ void cp16(uint32_t dst, const void* src) {
    asm volatile("cp.async.cg.shared.global [%0], [%1], 16;\n" :: "r"(dst), "l"(src));
}
__device__ __forceinline__ void ldsm4(uint32_t& r0, uint32_t& r1, uint32_t& r2, uint32_t& r3,
                                      uint32_t addr) {
    asm volatile("ldmatrix.sync.aligned.m8n8.x4.shared.b16 {%0,%1,%2,%3}, [%4];"
        : "=r"(r0), "=r"(r1), "=r"(r2), "=r"(r3) : "r"(addr));
}
__device__ __forceinline__ void ldsm4t(uint32_t& r0, uint32_t& r1, uint32_t& r2, uint32_t& r3,
                                       uint32_t addr) {
    asm volatile("ldmatrix.sync.aligned.m8n8.x4.trans.shared.b16 {%0,%1,%2,%3}, [%4];"
        : "=r"(r0), "=r"(r1), "=r"(r2), "=r"(r3) : "r"(addr));
}
__device__ __forceinline__ void mma16816(float* c, const uint32_t* a, uint32_t b0, uint32_t b1) {
    asm volatile("mma.sync.aligned.m16n8k16.row.col.f32.bf16.bf16.f32 "
        "{%0,%1,%2,%3}, {%4,%5,%6,%7}, {%8,%9}, {%0,%1,%2,%3};"
        : "+f"(c[0]), "+f"(c[1]), "+f"(c[2]), "+f"(c[3])
        : "r"(a[0]), "r"(a[1]), "r"(a[2]), "r"(a[3]), "r"(b0), "r"(b1));
}
__device__ __forceinline__ void mma16816h(float* c, const uint32_t* a, uint32_t b0, uint32_t b1) {
    asm volatile("mma.sync.aligned.m16n8k16.row.col.f32.f16.f16.f32 "
        "{%0,%1,%2,%3}, {%4,%5,%6,%7}, {%8,%9}, {%0,%1,%2,%3};"
        : "+f"(c[0]), "+f"(c[1]), "+f"(c[2]), "+f"(c[3])
        : "r"(a[0]), "r"(a[1]), "r"(a[2]), "r"(a[3]), "r"(b0), "r"(b1));
}
__device__ __forceinline__ uint32_t packex2h2(float tlo, float thi) {
    uint32_t t, r;
    asm("cvt.rn.f16x2.f32 %0, %1, %2;" : "=r"(t) : "f"(thi), "f"(tlo));
    asm("ex2.approx.f16x2 %0, %1;" : "=r"(r) : "r"(t));
    return r;
}
__device__ __forceinline__ void split2(float x, __nv_bfloat16& h, __nv_bfloat16& l) {
    h = __float2bfloat16(x);
    l = __float2bfloat16(x - __bfloat162float(h));
}

// ---------------- scratch ----------------
__device__ float g_lat [B*LQ*D];
__device__ float g_tmpf[B*LQ*D];
__device__ float g_bc  [KVN];
__device__ float g_zerob[D_IN];

__device__ __align__(256) __half g_mask6[NB*LQ*T];
__device__ __align__(256) __half g_tokh [B*T*D_IN];
__device__ __align__(256) __half g_tmph [B*LQ*D];
__device__ __align__(256) __half g_hidh [B*LQ*HID];
__device__ __align__(256) __half g_ath  [B*LQ*D];
__device__ __align__(256) __half g_qh   [B*LQ*D];
__device__ __align__(256) __half g_kallh[(size_t)B*T*(NB*D)];
__device__ __align__(256) __half g_vallh[(size_t)B*T*(NB*D)];
__device__ __align__(256) __half g_sqh  [B*LQ*3*D];
// weights: [N, 2K] = [hi(K) | lo(K)] fp16
__device__ __align__(256) __half g_wch  [KVN*2*D_IN];
__device__ __align__(256) __half g_wxqkvh[NB*3*D*2*D];
__device__ __align__(256) __half g_wxoh  [NB*D*2*D];
__device__ __align__(256) __half g_wmx1h [NB*HID*2*D];
__device__ __align__(256) __half g_wmx2h [NB*D*2*HID];
__device__ __align__(256) __half g_wsqkvh[NB*3*D*2*D];
__device__ __align__(256) __half g_wsoh  [NB*D*2*D];
__device__ __align__(256) __half g_wms1h [NB*HID*2*D];
__device__ __align__(256) __half g_wms2h [NB*D*2*HID];
// bf16-split only for the weight-fold GEMM
__device__ __align__(256) __nv_bfloat16 g_wkv2[NB*2*D*2*D];
__device__ __align__(256) __nv_bfloat16 g_wpT2[D_IN*2*D];

// ---------------- reductions ----------------
__device__ __forceinline__ float block_sum256(float v, float* sh) {
    #pragma unroll
    for (int o = 16; o; o >>= 1) v += __shfl_xor_sync(0xffffffffu, v, o);
    if ((threadIdx.x & 31) == 0) sh[threadIdx.x >> 5] = v;
    __syncthreads();
    float t = (threadIdx.x < 8) ? sh[threadIdx.x] : 0.f;
    if (threadIdx.x < 32) {
        #pragma unroll
        for (int o = 4; o; o >>= 1) t += __shfl_xor_sync(0xffffffffu, t, o);
        if (threadIdx.x == 0) sh[0] = t;
    }
    __syncthreads();
    float r = sh[0];
    __syncthreads();
    return r;
}

// ================= fp16 GEMM: C = A·W^T + bias =================
// A [M,K] fp16 single. W [N, 2K] fp16 [hi|lo]; NP=1 uses hi only, NP=2 adds A·Wl.
// EPI: 0 = bias->fp16  1 = bias+gelu->fp16  2 = bias+residual (fp32 C inplace)
#define BK 32
#define AST 40

// ---- 128x128 tile, 256 threads (KV production) ----
#define STG (128 * AST * 2)
#define NSTAGE 4
#define GSM (NSTAGE * 2 * STG)

template<int EPI, int NP>
__global__ __launch_bounds__(256)
void gemm_b16(const __half* __restrict__ A, int ldA,
              const __half* __restrict__ W, int ldW,
              const float* __restrict__ bias,
              float* __restrict__ C, __half* __restrict__ Ch, int N, int K)
{
    extern __shared__ __align__(256) char smraw[];
    const uint32_t base = smem_u32(smraw);
    const int tid = threadIdx.x;
    const int bm = blockIdx.y * 128, bn = blockIdx.x * 128;
    const int lane = tid & 31, warp = tid >> 5;
    const int wm = warp & 3, wn = warp >> 2;
    const int nkc = K / BK;
    const int nch = NP * nkc;

    float acc[2][8][4];
    #pragma unroll
    for (int i = 0; i < 2; i++)
        #pragma unroll
        for (int j = 0; j < 8; j++)
            #pragma unroll
            for (int k = 0; k < 4; k++) acc[i][j][k] = 0.f;

    auto issue_load = [&](int i, int st) {
        int s = i / nkc, kc = i - s * nkc;
        uint32_t smA = base + st * (2 * STG);
        uint32_t smB = smA + STG;
        const __half* As = A + (size_t)bm * ldA + kc * BK;
        const __half* Ws = W + (size_t)bn * ldW + s * K + kc * BK;
        #pragma unroll
        for (int j = 0; j < 2; j++) {
            int u = j * 256 + tid;
            int r = u >> 2, cc = (u & 3) * 8;
            cp16(smA + (uint32_t)(r * AST + cc) * 2, As + (size_t)r * ldA + cc);
            cp16(smB + (uint32_t)(r * AST + cc) * 2, Ws + (size_t)r * ldW + cc);
        }
        asm volatile("cp.async.commit_group;\n" ::: "memory");
    };

    const int arow = wm * 32 + ((lane >> 3) & 1) * 8 + (lane & 7);
    const int akof = ((lane >> 4) & 1) * 8;
    const int brow = wn * 64 + ((lane >> 4) & 1) * 8 + (lane & 7);
    const int bkof = ((lane >> 3) & 1) * 8;

    #pragma unroll
    for (int s = 0; s < NSTAGE - 1; s++) issue_load(s, s);

    for (int i = 0; i < nch; i++) {
        int rem = nch - 1 - i;
        if (rem >= 2)      asm volatile("cp.async.wait_group 2;\n" ::: "memory");
        else if (rem == 1) asm volatile("cp.async.wait_group 1;\n" ::: "memory");
        else               asm volatile("cp.async.wait_group 0;\n" ::: "memory");
        __syncthreads();
        if (i + NSTAGE - 1 < nch) issue_load(i + NSTAGE - 1, (i + NSTAGE - 1) % NSTAGE);

        uint32_t smA = base + (i % NSTAGE) * (2 * STG);
        uint32_t smB = smA + STG;
        #pragma unroll
        for (int kk = 0; kk < 2; kk++) {
            const int k0 = kk * 16;
            uint32_t a[2][4], b[4][4];
            #pragma unroll
            for (int fm = 0; fm < 2; fm++)
                ldsm4(a[fm][0], a[fm][1], a[fm][2], a[fm][3],
                      smA + (uint32_t)((arow + fm * 16) * AST + k0 + akof) * 2);
            #pragma unroll
            for (int fb = 0; fb < 4; fb++)
                ldsm4(b[fb][0], b[fb][1], b[fb][2], b[fb][3],
                      smB + (uint32_t)((brow + fb * 16) * AST + k0 + bkof) * 2);
            #pragma unroll
            for (int fm = 0; fm < 2; fm++)
                #pragma unroll
                for (int fn = 0; fn < 8; fn++)
                    mma16816h(acc[fm][fn], a[fm], b[fn >> 1][(fn & 1) * 2],
                              b[fn >> 1][(fn & 1) * 2 + 1]);
        }
    }

    const int lr = lane >> 2, lc = (lane & 3) * 2;
    #pragma unroll
    for (int fm = 0; fm < 2; fm++) {
        #pragma unroll
        for (int fn = 0; fn < 8; fn++) {
            float* cc = acc[fm][fn];
            int m0 = bm + wm * 32 + fm * 16 + lr;
            int n0 = bn + wn * 64 + fn * 8 + lc;
            float b0 = bias[n0], b1 = bias[n0 + 1];
            float v00 = cc[0] + b0, v01 = cc[1] + b1;
            float v10 = cc[2] + b0, v11 = cc[3] + b1;
            if (EPI == 1) {
                v00 = 0.5f * v00 * (1.0f + erff(v00 * 0.70710678118654752f));
                v01 = 0.5f * v01 * (1.0f + erff(v01 * 0.70710678118654752f));
                v10 = 0.5f * v10 * (1.0f + erff(v10 * 0.70710678118654752f));
                v11 = 0.5f * v11 * (1.0f + erff(v11 * 0.70710678118654752f));
            }
            if (EPI == 2) {
                float2 r0 = *(const float2*)&C[(size_t)m0 * N + n0];
                float2 r1 = *(const float2*)&C[(size_t)(m0 + 8) * N + n0];
                *(float2*)&C[(size_t)m0 * N + n0]       = make_float2(v00 + r0.x, v01 + r0.y);
                *(float2*)&C[(size_t)(m0 + 8) * N + n0] = make_float2(v10 + r1.x, v11 + r1.y);
            } else {
                *(half2*)&Ch[(size_t)m0 * N + n0]       = __floats2half2_rn(v00, v01);
                *(half2*)&Ch[(size_t)(m0 + 8) * N + n0] = __floats2half2_rn(v10, v11);
            }
        }
    }
}

// ---- 64x128 tile, 128 threads (per-block GEMMs, NP=2 W-split) ----
#define NSTAGE_H 3
#define ASTGH (64 * AST * 2)
#define BSTGH (128 * AST * 2)
#define GSMH (NSTAGE_H * (ASTGH + BSTGH))

template<int EPI, int NP>
__global__ __launch_bounds__(128)
void gemm_h16(const __half* __restrict__ A, int ldA,
              const __half* __restrict__ W, int ldW,
              const float* __restrict__ bias,
              float* __restrict__ C, __half* __restrict__ Ch, int N, int K)
{
    extern __shared__ __align__(256) char smraw[];
    const uint32_t base = smem_u32(smraw);
    const int tid = threadIdx.x;
    const int bm = blockIdx.y * 64, bn = blockIdx.x * 128;
    const int lane = tid & 31, warp = tid >> 5;
    const int wm = warp & 1, wn = warp >> 1;
    const int nkc = K / BK;
    const int nch = NP * nkc;

    float acc[2][8][4];
    #pragma unroll
    for (int i = 0; i < 2; i++)
        #pragma unroll
        for (int j = 0; j < 8; j++)
            #pragma unroll
            for (int k = 0; k < 4; k++) acc[i][j][k] = 0.f;

    auto issue_load = [&](int i, int st) {
        int s = i / nkc, kc = i - s * nkc;
        uint32_t smA = base + st * (ASTGH + BSTGH);
        uint32_t smB = smA + ASTGH;
        const __half* As = A + (size_t)bm * ldA + kc * BK;
        const __half* Ws = W + (size_t)bn * ldW + s * K + kc * BK;
        #pragma unroll
        for (int j = 0; j < 2; j++) {
            int u = j * 128 + tid;
            int r = u >> 2, cc = (u & 3) * 8;
            cp16(smA + (uint32_t)(r * AST + cc) * 2, As + (size_t)r * ldA + cc);
        }
        #pragma unroll
        for (int j = 0; j < 4; j++) {
            int u = j * 128 + tid;
            int r = u >> 2, cc = (u & 3) * 8;
            cp16(smB + (uint32_t)(r * AST + cc) * 2, Ws + (size_t)r * ldW + cc);
        }
        asm volatile("cp.async.commit_group;\n" ::: "memory");
    };

    const int arow = wm * 32 + ((lane >> 3) & 1) * 8 + (lane & 7);
    const int akof = ((lane >> 4) & 1) * 8;
    const int brow = wn * 64 + ((lane >> 4) & 1) * 8 + (lane & 7);
    const int bkof = ((lane >> 3) & 1) * 8;

    #pragma unroll
    for (int s = 0; s < NSTAGE_H - 1; s++) issue_load(s, s);

    for (int i = 0; i < nch; i++) {
        int rem = nch - 1 - i;
        if (rem >= 1) asm volatile("cp.async.wait_group 1;\n" ::: "memory");
        else          asm volatile("cp.async.wait_group 0;\n" ::: "memory");
        __syncthreads();
        if (i + NSTAGE_H - 1 < nch) issue_load(i + NSTAGE_H - 1, (i + NSTAGE_H - 1) % NSTAGE_H);

        uint32_t smA = base + (i % NSTAGE_H) * (ASTGH + BSTGH);
        uint32_t smB = smA + ASTGH;
        #pragma unroll
        for (int kk = 0; kk < 2; kk++) {
            const int k0 = kk * 16;
            uint32_t a[2][4], b[4][4];
            #pragma unroll
            for (int fm = 0; fm < 2; fm++)
                ldsm4(a[fm][0], a[fm][1], a[fm][2], a[fm][3],
                      smA + (uint32_t)((arow + fm * 16) * AST + k0 + akof) * 2);
            #pragma unroll
            for (int fb = 0; fb < 4; fb++)
                ldsm4(b[fb][0], b[fb][1], b[fb][2], b[fb][3],
                      smB + (uint32_t)((brow + fb * 16) * AST + k0 + bkof) * 2);
            #pragma unroll
            for (int fm = 0; fm < 2; fm++)
                #pragma unroll
                for (int fn = 0; fn < 8; fn++)
                    mma16816h(acc[fm][fn], a[fm], b[fn >> 1][(fn & 1) * 2],
                              b[fn >> 1][(fn & 1) * 2 + 1]);
        }
    }

    const int lr = lane >> 2, lc = (lane & 3) * 2;
    #pragma unroll
    for (int fm = 0; fm < 2; fm++) {
        #pragma unroll
        for (int fn = 0; fn < 8; fn++) {
            float* cc = acc[fm][fn];
            int m0 = bm + wm * 32 + fm * 16 + lr;
            int n0 = bn + wn * 64 + fn * 8 + lc;
            float b0 = bias[n0], b1 = bias[n0 + 1];
            float v00 = cc[0] + b0, v01 = cc[1] + b1;
            float v10 = cc[2] + b0, v11 = cc[3] + b1;
            if (EPI == 1) {
                v00 = 0.5f * v00 * (1.0f + erff(v00 * 0.70710678118654752f));
                v01 = 0.5f * v01 * (1.0f + erff(v01 * 0.70710678118654752f));
                v10 = 0.5f * v10 * (1.0f + erff(v10 * 0.70710678118654752f));
                v11 = 0.5f * v11 * (1.0f + erff(v11 * 0.70710678118654752f));
            }
            if (EPI == 2) {
                float2 r0 = *(const float2*)&C[(size_t)m0 * N + n0];
                float2 r1 = *(const float2*)&C[(size_t)(m0 + 8) * N + n0];
                *(float2*)&C[(size_t)m0 * N + n0]       = make_float2(v00 + r0.x, v01 + r0.y);
                *(float2*)&C[(size_t)(m0 + 8) * N + n0] = make_float2(v10 + r1.x, v11 + r1.y);
            } else {
                *(half2*)&Ch[(size_t)m0 * N + n0]       = __floats2half2_rn(v00, v01);
                *(half2*)&Ch[(size_t)(m0 + 8) * N + n0] = __floats2half2_rn(v10, v11);
            }
        }
    }
}

// ---- bf16-split 3-pass GEMM (64x128), hi|lo fp16 output — weight fold ONLY ----
__global__ __launch_bounds__(128)
void gemm_bf(const __nv_bfloat16* __restrict__ A2, int ldA,
             const __nv_bfloat16* __restrict__ W2, int ldW,
             const float* __restrict__ bias,
             __half* __restrict__ C3, int N, int K)
{
    extern __shared__ __align__(256) char smraw[];
    const uint32_t base = smem_u32(smraw);
    const int tid = threadIdx.x;
    const int bm = blockIdx.y * 64, bn = blockIdx.x * 128;
    const int lane = tid & 31, warp = tid >> 5;
    const int wm = warp & 1, wn = warp >> 1;
    const int nkc = K / BK;
    const int nch = 3 * nkc;

    float acc[2][8][4];
    #pragma unroll
    for (int i = 0; i < 2; i++)
        #pragma unroll
        for (int j = 0; j < 8; j++)
            #pragma unroll
            for (int k = 0; k < 4; k++) acc[i][j][k] = 0.f;

    auto issue_load = [&](int i, int st) {
        int s = i / nkc, kc = i - s * nkc;
        int ao = ((s == 2) ? K : 0) + kc * BK;
        int wo = ((s == 1) ? K : 0) + kc * BK;
        uint32_t smA = base + st * (ASTGH + BSTGH);
        uint32_t smB = smA + ASTGH;
        const __nv_bfloat16* As = A2 + (size_t)bm * ldA + ao;
        const __nv_bfloat16* Ws = W2 + (size_t)bn * ldW + wo;
        #pragma unroll
        for (int j = 0; j < 2; j++) {
            int u = j * 128 + tid;
            int r = u >> 2, cc = (u & 3) * 8;
            cp16(smA + (uint32_t)(r * AST + cc) * 2, As + (size_t)r * ldA + cc);
        }
        #pragma unroll
        for (int j = 0; j < 4; j++) {
            int u = j * 128 + tid;
            int r = u >> 2, cc = (u & 3) * 8;
            cp16(smB + (uint32_t)(r * AST + cc) * 2, Ws + (size_t)r * ldW + cc);
        }
        asm volatile("cp.async.commit_group;\n" ::: "memory");
    };

    const int arow = wm * 32 + ((lane >> 3) & 1) * 8 + (lane & 7);
    const int akof = ((lane >> 4) & 1) * 8;
    const int brow = wn * 64 + ((lane >> 4) & 1) * 8 + (lane & 7);
    const int bkof = ((lane >> 3) & 1) * 8;

    #pragma unroll
    for (int s = 0; s < NSTAGE_H - 1; s++) issue_load(s, s);

    for (int i = 0; i < nch; i++) {
        int rem = nch - 1 - i;
        if (rem >= 1) asm volatile("cp.async.wait_group 1;\n" ::: "memory");
        else          asm volatile("cp.async.wait_group 0;\n" ::: "memory");
        __syncthreads();
        if (i + NSTAGE_H - 1 < nch) issue_load(i + NSTAGE_H - 1, (i + NSTAGE_H - 1) % NSTAGE_H);

        uint32_t smA = base + (i % NSTAGE_H) * (ASTGH + BSTGH);
        uint32_t smB = smA + ASTGH;
        #pragma unroll
        for (int kk = 0; kk < 2; kk++) {
            const int k0 = kk * 16;
            uint32_t a[2][4], b[4][4];
            #pragma unroll
            for (int fm = 0; fm < 2; fm++)
                ldsm4(a[fm][0], a[fm][1], a[fm][2], a[fm][3],
                      smA + (uint32_t)((arow + fm * 16) * AST + k0 + akof) * 2);
            #pragma unroll
            for (int fb = 0; fb < 4; fb++)
                ldsm4(b[fb][0], b[fb][1], b[fb][2], b[fb][3],
                      smB + (uint32_t)((brow + fb * 16) * AST + k0 + bkof) * 2);
            #pragma unroll
            for (int fm = 0; fm < 2; fm++)
                #pragma unroll
                for (int fn = 0; fn < 8; fn++)
                    mma16816(acc[fm][fn], a[fm], b[fn >> 1][(fn & 1) * 2],
                             b[fn >> 1][(fn & 1) * 2 + 1]);
        }
    }

    // epilogue: write fp16 hi + fp16 lo at [m, 2N] = [hi(N) | lo(N)]
    const int lr = lane >> 2, lc = (lane & 3) * 2;
    #pragma unroll
    for (int fm = 0; fm < 2; fm++) {
        #pragma unroll
        for (int fn = 0; fn < 8; fn++) {
            float* cc = acc[fm][fn];
            int m0 = bm + wm * 32 + fm * 16 + lr;
            int n0 = bn + wn * 64 + fn * 8 + lc;
            float b0 = bias[n0], b1 = bias[n0 + 1];
            #pragma unroll
            for (int rr = 0; rr < 2; rr++) {
                float va = cc[rr * 2] + b0, vb = cc[rr * 2 + 1] + b1;
                __half ha = __float2half(va), hb = __float2half(vb);
                __half la = __float2half(va - __half2float(ha));
                __half lb = __float2half(vb - __half2float(hb));
                size_t row = (size_t)(m0 + rr * 8) * 2 * N;
                *(half2*)&C3[row + n0]     = half2(ha, hb);
                *(half2*)&C3[row + N + n0] = half2(la, lb);
            }
        }
    }
}

// ================= fused flash attention (fp16, BQ=256, 512 threads) =================
#define BQ 256
#define BKC 64
#define QST 72
#define FTILEQ (256 * QST * 2)        // 36864 B
#define FTILE (64 * QST * 2)          // 9216 B
#define FSTG (2 * FTILE)
#define FA_SMEM (FTILEQ + 2 * FSTG + 64)

__global__ __launch_bounds__(512)
void fattn(const __half* __restrict__ Qp, int ldq,
           const __half* __restrict__ Kp, int ldk,
           const __half* __restrict__ Vh, int ldv,
           const __half* __restrict__ pm, __half* __restrict__ Oh, int Tk)
{
    extern __shared__ __align__(256) char smraw[];
    const uint32_t base = smem_u32(smraw);
    const int tid = threadIdx.x, lane = tid & 31, warp = tid >> 5;
    const int bh = (int)blockIdx.y, b = bh >> 3, h = bh & 7;
    const int q0 = (int)blockIdx.x * BQ;

    const __half* Qb = Qp + (size_t)(b * LQ + q0) * ldq + h * HD;
    const __half* Kb = Kp + (size_t)b * Tk * ldk + h * HD;
    const __half* Vb = Vh + (size_t)b * Tk * ldv + h * HD;

    // Q tile (256 rows)
    #pragma unroll
    for (int j = 0; j < 4; j++) {
        int u = j * 512 + tid, r = u >> 3, c8 = (u & 7) * 8;
        cp16(base + (uint32_t)(r * QST + c8) * 2, Qb + (size_t)r * ldq + c8);
    }
    asm volatile("cp.async.commit_group;\n" ::: "memory");

    // ones columns (64..71) in both stages' V tiles
    if (tid < 128) {
        int r = tid >> 1, cq = (tid & 1) * 4;
        #pragma unroll
        for (int st = 0; st < 2; st++) {
            size_t off = (size_t)FTILEQ + (size_t)st * FSTG + FTILE
                       + (size_t)(r * QST + 64 + cq) * 2;
            *(uint2*)(smraw + off) = make_uint2(0x3C003C00u, 0x3C003C00u);
        }
    }

    const int nc = Tk / BKC;
    auto load_chunk = [&](int ci, int st) {
        uint32_t sb = base + FTILEQ + st * FSTG;
        const __half* Kc = Kb + (size_t)ci * BKC * ldk;
        const __half* Vc = Vb + (size_t)ci * BKC * ldv;
        int r = tid >> 3, c8 = (tid & 7) * 8;
        uint32_t off = (uint32_t)(r * QST + c8) * 2;
        cp16(sb + off,         Kc + (size_t)r * ldk + c8);
        cp16(sb + FTILE + off, Vc + (size_t)r * ldv + c8);
        asm volatile("cp.async.commit_group;\n" ::: "memory");
    };

    load_chunk(0, 0);
    asm volatile("cp.async.wait_group 1;\n" ::: "memory");
    __syncthreads();

    const int qrow = warp * 16 + ((lane >> 3) & 1) * 8 + (lane & 7);
    const int qko  = ((lane >> 4) & 1) * 8;
    uint32_t qf[4][4];
    #pragma unroll
    for (int ds = 0; ds < 4; ds++)
        ldsm4(qf[ds][0], qf[ds][1], qf[ds][2], qf[ds][3],
              base + (uint32_t)(qrow * QST + ds * 16 + qko) * 2);

    load_chunk(1, 1);

    float o[8][4], osum[4];
    #pragma unroll
    for (int i = 0; i < 8; i++)
        #pragma unroll
        for (int j = 0; j < 4; j++) o[i][j] = 0.f;
    #pragma unroll
    for (int j = 0; j < 4; j++) osum[j] = 0.f;

    const float SC  = 0.125f * 1.44269504088896f;
    const float L2E = 1.44269504088896f;
    const int lr = lane >> 2, lc = (lane & 3) * 2;
    const int krow = ((lane >> 4) & 1) * 8 + (lane & 7);
    const int kko  = ((lane >> 3) & 1) * 8;
    const int vrow = lane & 15;
    const int vco  = ((lane >> 4) & 1) * 8;
    const int qr_g = q0 + warp * 16 + lr;

    for (int ci = 0; ci < nc; ci++) {
        if (ci == nc - 1) asm volatile("cp.async.wait_group 0;\n" ::: "memory");
        else              asm volatile("cp.async.wait_group 1;\n" ::: "memory");
        __syncthreads();

        uint32_t sb = base + FTILEQ + (ci & 1) * FSTG;

        // ---- S = Q·K^T ----
        float s[8][4];
        #pragma unroll
        for (int i = 0; i < 8; i++)
            #pragma unroll
            for (int j = 0; j < 4; j++) s[i][j] = 0.f;
        #pragma unroll
        for (int ds = 0; ds < 4; ds++) {
            #pragma unroll
            for (int g = 0; g < 4; g++) {
                uint32_t b0, b1, b2, b3;
                ldsm4(b0, b1, b2, b3,
                      sb + (uint32_t)((g * 16 + krow) * QST + ds * 16 + kko) * 2);
                mma16816h(s[2 * g],     qf[ds], b0, b1);
                mma16816h(s[2 * g + 1], qf[ds], b2, b3);
            }
        }

        // ---- probs as fp16 fragments ----
        uint32_t ph[4][4];
        #pragma unroll
        for (int nt = 0; nt < 8; nt++) {
            float t0 = s[nt][0] * SC, t1 = s[nt][1] * SC;
            float t2 = s[nt][2] * SC, t3 = s[nt][3] * SC;
            if (pm) {
                const __half* pmr = pm + (size_t)qr_g * Tk + ci * BKC + nt * 8 + lc;
                float2 m0 = __half22float2(*(const half2*)pmr);
                float2 m1 = __half22float2(*(const half2*)(pmr + (size_t)8 * Tk));
                t0 = fmaf(m0.x, L2E, t0); t1 = fmaf(m0.y, L2E, t1);
                t2 = fmaf(m1.x, L2E, t2); t3 = fmaf(m1.y, L2E, t3);
            }
            int j = nt >> 1, qi = (nt & 1) * 2;
            ph[j][qi]     = packex2h2(t0, t1);
            ph[j][qi + 1] = packex2h2(t2, t3);
        }

        // ---- O += P·V + row sums via ones columns ----
        uint32_t vb = sb + FTILE;
        #pragma unroll
        for (int ks = 0; ks < 4; ks++) {
            const uint32_t* pf = ph[ks];
            #pragma unroll
            for (int g = 0; g < 4; g++) {
                uint32_t b0, b1, b2, b3;
                ldsm4t(b0, b1, b2, b3,
                       vb + (uint32_t)((ks * 16 + vrow) * QST + g * 16 + vco) * 2);
                mma16816h(o[2 * g],     pf, b0, b1);
                mma16816h(o[2 * g + 1], pf, b2, b3);
            }
            {
                uint32_t b0, b1, b2, b3;
                ldsm4t(b0, b1, b2, b3,
                       vb + (uint32_t)((ks * 16 + vrow) * QST + 64 + vco) * 2);
                mma16816h(osum, pf, b0, b1);
            }
        }

        __syncthreads();
        if (ci + 2 < nc) load_chunk(ci + 2, ci & 1);
    }

    float inv0 = 1.0f / osum[0], inv1 = 1.0f / osum[2];

    const size_t row0 = (size_t)(b * LQ + qr_g);
    #pragma unroll
    for (int nt = 0; nt < 8; nt++) {
        int col = h * HD + nt * 8 + lc;
        *(half2*)&Oh[row0 * D + col] =
            __floats2half2_rn(o[nt][0] * inv0, o[nt][1] * inv0);
        *(half2*)&Oh[(row0 + 8) * D + col] =
            __floats2half2_rn(o[nt][2] * inv1, o[nt][3] * inv1);
    }
}

// ---------------- elementwise: fp32 [rows,K] -> fp16 [rows,2K] hi|lo ----------------
__global__ void hsplit(const float* __restrict__ src, __half* __restrict__ dst, int K)
{
    int c = blockIdx.x * 256 + threadIdx.x;
    int r = blockIdx.y;
    float x = src[(size_t)r * K + c];
    __half h = __float2half(x);
    __half l = __float2half(x - __half2float(h));
    dst[(size_t)r * 2 * K + c] = h;
    dst[(size_t)r * 2 * K + K + c] = l;
}

__global__ void hconv(const float* __restrict__ src, __half* __restrict__ dst)
{
    size_t i = (size_t)blockIdx.x * 256 + threadIdx.x;
    dst[i] = __float2half(src[i]);
}

// split KV rows of xw_qkv -> g_wkv2 (per block: rows D..3D), bf16 hi|lo
__global__ void split_kv(const float* __restrict__ xw_qkv, __nv_bfloat16* __restrict__ dst)
{
    int c = blockIdx.x * 256 + threadIdx.x;
    int g = blockIdx.y;
    int i = g / (2 * D), r = g % (2 * D);
    float x = xw_qkv[((size_t)i * 3 * D + D + r) * D + c];
    __nv_bfloat16 h, l; split2(x, h, l);
    dst[(size_t)g * 2 * D + c] = h;
    dst[(size_t)g * 2 * D + D + c] = l;
}

// transpose+split: proj_w[D, D_IN] -> wT2[D_IN, 2*D]
__global__ void tsplit_proj(const float* __restrict__ pw, __nv_bfloat16* __restrict__ wT2)
{
    int k = blockIdx.x * 256 + threadIdx.x;
    int c = blockIdx.y;
    float x = pw[(size_t)k * D_IN + c];
    __nv_bfloat16 h, l; split2(x, h, l);
    wT2[(size_t)c * 2 * D + k] = h;
    wT2[(size_t)c * 2 * D + D + k] = l;
}

// folded KV bias for [Kall | Vall] layout
__global__ void kvbias_kernel(const float* __restrict__ xw_qkv, const float* __restrict__ xb_qkv,
                              const float* __restrict__ proj_b, float* __restrict__ bc)
{
    __shared__ float sh[32];
    int g = blockIdx.x;
    int wrow;
    if (g < 3072) { int i = g >> 9, n = g & 511; wrow = i * 3 * D + D + n; }
    else          { int gg = g - 3072; int i = gg >> 9, n = gg & 511; wrow = i * 3 * D + 2 * D + n; }
    const float* wr = xw_qkv + (size_t)wrow * D;
    float s = 0.f;
    for (int k = threadIdx.x; k < D; k += 256) s += wr[k] * proj_b[k];
    float tot = block_sum256(s, sh);
    if (threadIdx.x == 0) bc[g] = tot + xb_qkv[wrow];
}

// ---------------- LayerNorm -> fp16 ----------------
__global__ void ln_half(const float* __restrict__ x, const float* __restrict__ g,
                        const float* __restrict__ b, __half* __restrict__ y)
{
    __shared__ float sh[32];
    const int row = blockIdx.x, tid = threadIdx.x;
    const float* xr = x + (size_t)row * D;
    float2 v = *(const float2*)&xr[tid * 2];
    float total = block_sum256(v.x + v.y, sh);
    float mean = total * (1.0f / D);
    float d0 = v.x - mean, d1 = v.y - mean;
    float sq = block_sum256(d0 * d0 + d1 * d1, sh);
    float inv = rsqrtf(sq * (1.0f / D) + 1e-5f);
    float2 go = *(const float2*)&g[tid * 2];
    float2 bo = *(const float2*)&b[tid * 2];
    ((half2*)(y + (size_t)row * D))[tid] =
        __floats2half2_rn(d0 * inv * go.x + bo.x, d1 * inv * go.y + bo.y);
}

// ---------------- plain LayerNorm (final) ----------------
__global__ void ln_kernel(const float* __restrict__ x, const float* __restrict__ g,
                          const float* __restrict__ b, float* __restrict__ y)
{
    __shared__ float sh[32];
    const int row = blockIdx.x, tid = threadIdx.x;
    const float* xr = x + (size_t)row * D;
    float2 v = *(const float2*)&xr[tid * 2];
    float total = block_sum256(v.x + v.y, sh);
    float mean = total * (1.0f / D);
    float d0 = v.x - mean, d1 = v.y - mean;
    float sq = block_sum256(d0 * d0 + d1 * d1, sh);
    float inv = rsqrtf(sq * (1.0f / D) + 1e-5f);
    float2 go = *(const float2*)&g[tid * 2];
    float2 bo = *(const float2*)&b[tid * 2];
    float2 o;
    o.x = d0 * inv * go.x + bo.x;
    o.y = d1 * inv * go.y + bo.y;
    *(float2*)&y[(size_t)row * D + tid * 2] = o;
}

// ---------------- all 6 relative-time masks (fp16 out) ----------------
__global__ void mask6_kernel(const float* __restrict__ rel_bias, const float* __restrict__ ms,
                             __half* __restrict__ pm6)
{
    int k = blockIdx.x * 256 + threadIdx.x;
    int q = blockIdx.y;
    int z = blockIdx.z;
    float tau = (float)q * (4095.0f / 255.0f);
    float dt = (float)k - tau;
    float c = fminf(fmaxf(dt, -128.f), 128.f);
    int idx = (int)c + 128;
    float zz = dt * (1.0f / 32.0f);
    float lg = logf(expf(-0.5f * zz * zz) + 1e-6f);
    pm6[(size_t)z * LQ * T + (size_t)q * T + k] =
        __float2half(ms[z] * (rel_bias[z * 257 + idx] + lg));
}

// ---------------- misc ----------------
__global__ void bcast_latents(const float* __restrict__ src, float* __restrict__ dst)
{
    int i = blockIdx.x * 256 + threadIdx.x;
    dst[i] = src[i % (LQ * D)];
}

__global__ void mean_kernel(const float* __restrict__ x, float* __restrict__ out)
{
    int i = blockIdx.x * 256 + threadIdx.x;
    int b = i / D, d = i % D;
    float s = 0.f;
    for (int q = 0; q < LQ; q++) s += x[((size_t)b * LQ + q) * D + d];
    out[i] = s * (1.0f / LQ);
}

// ---------------- host orchestration ----------------
extern "C" void kernel_launch(void* const* d_in, const int* in_sizes, int n_in,
                              void* d_out, int out_size)
{
    (void)in_sizes; (void)n_in; (void)out_size;
    const float* tokens     = (const float*)d_in[0];
    const float* proj_w     = (const float*)d_in[1];
    const float* proj_b     = (const float*)d_in[2];
    const float* latents    = (const float*)d_in[3];
    const float* lnx_g      = (const float*)d_in[4];
    const float* lnx_b      = (const float*)d_in[5];
    const float* xw_qkv     = (const float*)d_in[6];
    const float* xb_qkv     = (const float*)d_in[7];
    const float* xw_o       = (const float*)d_in[8];
    const float* xb_o       = (const float*)d_in[9];
    const float* rel_bias   = (const float*)d_in[10];
    const float* mask_scale = (const float*)d_in[11];
    const float* mx_w1      = (const float*)d_in[12];
    const float* mx_b1      = (const float*)d_in[13];
    const float* mx_w2      = (const float*)d_in[14];
    const float* mx_b2      = (const float*)d_in[15];
    const float* lns_g      = (const float*)d_in[16];
    const float* lns_b      = (const float*)d_in[17];
    const float* sw_qkv     = (const float*)d_in[18];
    const float* sb_qkv     = (const float*)d_in[19];
    const float* sw_o       = (const float*)d_in[20];
    const float* sb_o       = (const float*)d_in[21];
    const float* ms_w1      = (const float*)d_in[22];
    const float* ms_b1      = (const float*)d_in[23];
    const float* ms_w2      = (const float*)d_in[24];
    const float* ms_b2      = (const float*)d_in[25];
    const float* lno_g      = (const float*)d_in[26];
    const float* lno_b      = (const float*)d_in[27];
    float* out = (float*)d_out;

    cudaFuncSetAttribute(gemm_b16<0, 1>, cudaFuncAttributeMaxDynamicSharedMemorySize, GSM);
    cudaFuncSetAttribute(gemm_b16<0, 2>, cudaFuncAttributeMaxDynamicSharedMemorySize, GSM);
    cudaFuncSetAttribute(gemm_h16<0, 2>, cudaFuncAttributeMaxDynamicSharedMemorySize, GSMH);
    cudaFuncSetAttribute(gemm_h16<1, 2>, cudaFuncAttributeMaxDynamicSharedMemorySize, GSMH);
    cudaFuncSetAttribute(gemm_h16<2, 2>, cudaFuncAttributeMaxDynamicSharedMemorySize, GSMH);
    cudaFuncSetAttribute(gemm_bf,        cudaFuncAttributeMaxDynamicSharedMemorySize, GSMH);
    cudaFuncSetAttribute(fattn,          cudaFuncAttributeMaxDynamicSharedMemorySize, FA_SMEM);

    float *plat, *ptmpf, *pbc, *pzb;
    __half *pmask6, *ptokh, *ptmph, *phidh, *path, *pqh, *pkallh, *pvallh, *psqh, *pwch,
           *pwxqkvh, *pwxoh, *pwmx1h, *pwmx2h, *pwsqkvh, *pwsoh, *pwms1h, *pwms2h;
    __nv_bfloat16 *pwkv2, *pwpT2;
    cudaGetSymbolAddress((void**)&plat,    g_lat);
    cudaGetSymbolAddress((void**)&ptmpf,   g_tmpf);
    cudaGetSymbolAddress((void**)&pmask6,  g_mask6);
    cudaGetSymbolAddress((void**)&pbc,     g_bc);
    cudaGetSymbolAddress((void**)&pzb,     g_zerob);
    cudaGetSymbolAddress((void**)&ptokh,   g_tokh);
    cudaGetSymbolAddress((void**)&ptmph,   g_tmph);
    cudaGetSymbolAddress((void**)&phidh,   g_hidh);
    cudaGetSymbolAddress((void**)&path,    g_ath);
    cudaGetSymbolAddress((void**)&pqh,     g_qh);
    cudaGetSymbolAddress((void**)&pkallh,  g_kallh);
    cudaGetSymbolAddress((void**)&pvallh,  g_vallh);
    cudaGetSymbolAddress((void**)&psqh,    g_sqh);
    cudaGetSymbolAddress((void**)&pwch,    g_wch);
    cudaGetSymbolAddress((void**)&pwxqkvh, g_wxqkvh);
    cudaGetSymbolAddress((void**)&pwxoh,   g_wxoh);
    cudaGetSymbolAddress((void**)&pwmx1h,  g_wmx1h);
    cudaGetSymbolAddress((void**)&pwmx2h,  g_wmx2h);
    cudaGetSymbolAddress((void**)&pwsqkvh, g_wsqkvh);
    cudaGetSymbolAddress((void**)&pwsoh,   g_wsoh);
    cudaGetSymbolAddress((void**)&pwms1h,  g_wms1h);
    cudaGetSymbolAddress((void**)&pwms2h,  g_wms2h);
    cudaGetSymbolAddress((void**)&pwkv2,   g_wkv2);
    cudaGetSymbolAddress((void**)&pwpT2,   g_wpT2);

    const int BT = B * T, BL = B * LQ;

    // ---- upfront: weight hi|lo splits, token convert ----
    hsplit<<<dim3(D / 256,   NB * 3 * D), 256>>>(xw_qkv, pwxqkvh, D);
    hsplit<<<dim3(D / 256,   NB * D),     256>>>(xw_o,   pwxoh,   D);
    hsplit<<<dim3(D / 256,   NB * HID),   256>>>(mx_w1,  pwmx1h,  D);
    hsplit<<<dim3(HID / 256, NB * D),     256>>>(mx_w2,  pwmx2h,  HID);
    hsplit<<<dim3(D / 256,   NB * 3 * D), 256>>>(sw_qkv, pwsqkvh, D);
    hsplit<<<dim3(D / 256,   NB * D),     256>>>(sw_o,   pwsoh,   D);
    hsplit<<<dim3(D / 256,   NB * HID),   256>>>(ms_w1,  pwms1h,  D);
    hsplit<<<dim3(HID / 256, NB * D),     256>>>(ms_w2,  pwms2h,  HID);
    hconv<<<(BT * D_IN) / 256, 256>>>(tokens, ptokh);

    // ---- fold (3-pass bf16 -> fp16 hi|lo): Wc = Wkv·Wp, layout [Kall | Vall] ----
    split_kv<<<dim3(D / 256, NB * 2 * D), 256>>>(xw_qkv, pwkv2);
    tsplit_proj<<<dim3(D / 256, D_IN), 256>>>(proj_w, pwpT2);
    for (int i = 0; i < NB; i++) {
        gemm_bf<<<dim3(D_IN / 128, 512 / 64), 128, GSMH>>>(
            pwkv2 + (size_t)(i * 2 * D) * 2 * D, 2 * D,
            pwpT2, 2 * D, pzb, pwch + (size_t)(i * 512) * 2 * D_IN, D_IN, D);
        gemm_bf<<<dim3(D_IN / 128, 512 / 64), 128, GSMH>>>(
            pwkv2 + (size_t)(i * 2 * D + 512) * 2 * D, 2 * D,
            pwpT2, 2 * D, pzb, pwch + (size_t)(3072 + i * 512) * 2 * D_IN, D_IN, D);
    }
    kvbias_kernel<<<KVN, 256>>>(xw_qkv, xb_qkv, proj_b, pbc);

    // ---- Kall (single-pass, hi only) / Vall (2-pass W-split), K=256 ----
    gemm_b16<0, 1><<<dim3(3072 / 128, BT / 128), 256, GSM>>>(
        ptokh, D_IN, pwch, 2 * D_IN, pbc, nullptr, pkallh, 3072, D_IN);
    gemm_b16<0, 2><<<dim3(3072 / 128, BT / 128), 256, GSM>>>(
        ptokh, D_IN, pwch + (size_t)3072 * 2 * D_IN, 2 * D_IN, pbc + 3072,
        nullptr, pvallh, 3072, D_IN);

    mask6_kernel<<<dim3(T / 256, LQ, NB), 256>>>(rel_bias, mask_scale, pmask6);
    bcast_latents<<<(BL * D) / 256, 256>>>(latents, plat);

    for (int i = 0; i < NB; i++) {
        // ---- cross attention ----
        ln_half<<<BL, 256>>>(plat, lnx_g + i * D, lnx_b + i * D, ptmph);
        gemm_h16<0, 2><<<dim3(D / 128, BL / 64), 128, GSMH>>>(
            ptmph, D, pwxqkvh + (size_t)i * 3 * D * 2 * D, 2 * D,
            xb_qkv + (size_t)i * 3 * D, nullptr, pqh, D, D);
        fattn<<<dim3(LQ / BQ, B * H), 512, FA_SMEM>>>(
            pqh, D,
            pkallh + (size_t)i * 512, 3072,
            pvallh + (size_t)i * 512, 3072,
            pmask6 + (size_t)i * LQ * T, path, T);
        gemm_h16<2, 2><<<dim3(D / 128, BL / 64), 128, GSMH>>>(
            path, D, pwxoh + (size_t)i * D * 2 * D, 2 * D, xb_o + i * D,
            plat, nullptr, D, D);

        // ---- cross MLP (pre-LN reuses lnx params) ----
        ln_half<<<BL, 256>>>(plat, lnx_g + i * D, lnx_b + i * D, ptmph);
        gemm_h16<1, 2><<<dim3(HID / 128, BL / 64), 128, GSMH>>>(
            ptmph, D, pwmx1h + (size_t)i * HID * 2 * D, 2 * D, mx_b1 + i * HID,
            nullptr, phidh, HID, D);
        gemm_h16<2, 2><<<dim3(D / 128, BL / 64), 128, GSMH>>>(
            phidh, HID, pwmx2h + (size_t)i * D * 2 * HID, 2 * HID, mx_b2 + i * D,
            plat, nullptr, D, HID);

        // ---- self attention ----
        ln_half<<<BL, 256>>>(plat, lns_g + i * D, lns_b + i * D, ptmph);
        gemm_h16<0, 2><<<dim3((3 * D) / 128, BL / 64), 128, GSMH>>>(
            ptmph, D, pwsqkvh + (size_t)i * 3 * D * 2 * D, 2 * D,
            sb_qkv + (size_t)i * 3 * D, nullptr, psqh, 3 * D, D);
        fattn<<<dim3(LQ / BQ, B * H), 512, FA_SMEM>>>(
            psqh, 3 * D,
            psqh + D, 3 * D,
            psqh + 2 * D, 3 * D,
            nullptr, path, LQ);
        gemm_h16<2, 2><<<dim3(D / 128, BL / 64), 128, GSMH>>>(
            path, D, pwsoh + (size_t)i * D * 2 * D, 2 * D, sb_o + i * D,
            plat, nullptr, D, D);

        // ---- self MLP ----
        ln_half<<<BL, 256>>>(plat, lns_g + i * D, lns_b + i * D, ptmph);
        gemm_h16<1, 2><<<dim3(HID / 128, BL / 64), 128, GSMH>>>(
            ptmph, D, pwms1h + (size_t)i * HID * 2 * D, 2 * D, ms_b1 + i * HID,
            nullptr, phidh, HID, D);
        gemm_h16<2, 2><<<dim3(D / 128, BL / 64), 128, GSMH>>>(
            phidh, HID, pwms2h + (size_t)i * D * 2 * HID, 2 * HID, ms_b2 + i * D,
            plat, nullptr, D, HID);
    }

    // final LN + mean over latents
    ln_kernel<<<BL, 256>>>(plat, lno_g, lno_b, ptmpf);
    mean_kernel<<<(B * D) / 256, 256>>>(ptmpf, out);
}

// round 13
// speedup vs baseline: 1.2319x; 1.2319x over previous
#include <cuda_runtime.h>
#include <cuda_bf16.h>
#include <cuda_fp16.h>
#include <cstdint>
#include <math.h>

// ---------------- problem constants ----------------
#define B   8
#define T   4096
#define D_IN 256
#define D   512
#define LQ  256
#define H   8
#define HD  64
#define NB  6
#define HID 2048
#define KVN (NB * 2 * D)

// ---------------- helpers ----------------
__device__ __forceinline__ uint32_t smem_u32(const void* p) {
    uint32_t a;
    asm("{ .reg .u64 t; cvta.to.shared.u64 t, %1; cvt.u32.u64 %0, t; }" : "=r"(a) : "l"(p));
    return a;
}
__device__ __forceinline__ void cp16(uint32_t dst, const void* src) {
    asm volatile("cp.async.cg.shared.global [%0], [%1], 16;\n" :: "r"(dst), "l"(src));
}
__device__ __forceinline__ void ldsm4(uint32_t& r0, uint32_t& r1, uint32_t& r2, uint32_t& r3,
                                      uint32_t addr) {
    asm volatile("ldmatrix.sync.aligned.m8n8.x4.shared.b16 {%0,%1,%2,%3}, [%4];"
        : "=r"(r0), "=r"(r1), "=r"(r2), "=r"(r3) : "r"(addr));
}
__device__ __forceinline__ void ldsm4t(uint32_t& r0, uint32_t& r1, uint32_t& r2, uint32_t& r3,
                                       uint32_t addr) {
    asm volatile("ldmatrix.sync.aligned.m8n8.x4.trans.shared.b16 {%0,%1,%2,%3}, [%4];"
        : "=r"(r0), "=r"(r1), "=r"(r2), "=r"(r3) : "r"(addr));
}
__device__ __forceinline__ void mma16816(float* c, const uint32_t* a, uint32_t b0, uint32_t b1) {
    asm volatile("mma.sync.aligned.m16n8k16.row.col.f32.bf16.bf16.f32 "
        "{%0,%1,%2,%3}, {%4,%5,%6,%7}, {%8,%9}, {%0,%1,%2,%3};"
        : "+f"(c[0]), "+f"(c[1]), "+f"(c[2]), "+f"(c[3])
        : "r"(a[0]), "r"(a[1]), "r"(a[2]), "r"(a[3]), "r"(b0), "r"(b1));
}
__device__ __forceinline__ void mma16816h(float* c, const uint32_t* a, uint32_t b0, uint32_t b1) {
    asm volatile("mma.sync.aligned.m16n8k16.row.col.f32.f16.f16.f32 "
        "{%0,%1,%2,%3}, {%4,%5,%6,%7}, {%8,%9}, {%0,%1,%2,%3};"
        : "+f"(c[0]), "+f"(c[1]), "+f"(c[2]), "+f"(c[3])
        : "r"(a[0]), "r"(a[1]), "r"(a[2]), "r"(a[3]), "r"(b0), "r"(b1));
}
__device__ __forceinline__ uint32_t packex2h2(float tlo, float thi) {
    uint32_t t, r;
    asm("cvt.rn.f16x2.f32 %0, %1, %2;" : "=r"(t) : "f"(thi), "f"(tlo));
    asm("ex2.approx.f16x2 %0, %1;" : "=r"(r) : "r"(t));
    return r;
}
__device__ __forceinline__ void split2(float x, __nv_bfloat16& h, __nv_bfloat16& l) {
    h = __float2bfloat16(x);
    l = __float2bfloat16(x - __bfloat162float(h));
}

// ---------------- scratch ----------------
__device__ float g_lat [B*LQ*D];
__device__ float g_tmpf[B*LQ*D];
__device__ float g_bc  [KVN];
__device__ float g_zerob[D_IN];

__device__ __align__(256) __half g_mask6[NB*LQ*T];
__device__ __align__(256) __half g_tokh [B*T*D_IN];
__device__ __align__(256) __half g_tmph [B*LQ*D];
__device__ __align__(256) __half g_hidh [B*LQ*HID];
__device__ __align__(256) __half g_ath  [B*LQ*D];
__device__ __align__(256) __half g_qh   [B*LQ*D];
__device__ __align__(256) __half g_kallh[(size_t)B*T*(NB*D)];
__device__ __align__(256) __half g_vallh[(size_t)B*T*(NB*D)];
__device__ __align__(256) __half g_sqh  [B*LQ*3*D];
// weights: [N, 2K] = [hi(K) | lo(K)] fp16
__device__ __align__(256) __half g_wch  [KVN*2*D_IN];
__device__ __align__(256) __half g_wxqkvh[NB*3*D*2*D];
__device__ __align__(256) __half g_wxoh  [NB*D*2*D];
__device__ __align__(256) __half g_wmx1h [NB*HID*2*D];
__device__ __align__(256) __half g_wmx2h [NB*D*2*HID];
__device__ __align__(256) __half g_wsqkvh[NB*3*D*2*D];
__device__ __align__(256) __half g_wsoh  [NB*D*2*D];
__device__ __align__(256) __half g_wms1h [NB*HID*2*D];
__device__ __align__(256) __half g_wms2h [NB*D*2*HID];
// bf16-split only for the weight-fold GEMM
__device__ __align__(256) __nv_bfloat16 g_wkv2[NB*2*D*2*D];
__device__ __align__(256) __nv_bfloat16 g_wpT2[D_IN*2*D];

// ---------------- reductions ----------------
__device__ __forceinline__ float block_sum256(float v, float* sh) {
    #pragma unroll
    for (int o = 16; o; o >>= 1) v += __shfl_xor_sync(0xffffffffu, v, o);
    if ((threadIdx.x & 31) == 0) sh[threadIdx.x >> 5] = v;
    __syncthreads();
    float t = (threadIdx.x < 8) ? sh[threadIdx.x] : 0.f;
    if (threadIdx.x < 32) {
        #pragma unroll
        for (int o = 4; o; o >>= 1) t += __shfl_xor_sync(0xffffffffu, t, o);
        if (threadIdx.x == 0) sh[0] = t;
    }
    __syncthreads();
    float r = sh[0];
    __syncthreads();
    return r;
}

// ================= fp16 fused dual-W GEMM: C = A·(Wh+Wl)^T + bias =================
// A [M,K] fp16. W [N,2K] = [hi|lo]; each k-chunk loads A once + both W tiles and
// accumulates both products into one acc. NP=1 uses hi only.
#define BK 32
#define AST 40

// ---- 128x128 tile, 256 threads (KV production) ----
#define STG (128 * AST * 2)            // 10240
#define NSTAGE 3
#define GSM (NSTAGE * 3 * STG)         // 92160

template<int EPI, int NP>
__global__ __launch_bounds__(256)
void gemm_b16(const __half* __restrict__ A, int ldA,
              const __half* __restrict__ W, int ldW,
              const float* __restrict__ bias,
              float* __restrict__ C, __half* __restrict__ Ch, int N, int K)
{
    extern __shared__ __align__(256) char smraw[];
    const uint32_t base = smem_u32(smraw);
    const int tid = threadIdx.x;
    const int bm = blockIdx.y * 128, bn = blockIdx.x * 128;
    const int lane = tid & 31, warp = tid >> 5;
    const int wm = warp & 3, wn = warp >> 2;
    const int nch = K / BK;

    float acc[2][8][4];
    #pragma unroll
    for (int i = 0; i < 2; i++)
        #pragma unroll
        for (int j = 0; j < 8; j++)
            #pragma unroll
            for (int k = 0; k < 4; k++) acc[i][j][k] = 0.f;

    auto issue_load = [&](int kc, int st) {
        uint32_t smA = base + st * (3 * STG);
        uint32_t smBh = smA + STG;
        uint32_t smBl = smBh + STG;
        const __half* As = A + (size_t)bm * ldA + kc * BK;
        const __half* Wh = W + (size_t)bn * ldW + kc * BK;
        const __half* Wl = Wh + K;
        #pragma unroll
        for (int j = 0; j < 2; j++) {
            int u = j * 256 + tid;
            int r = u >> 2, cc = (u & 3) * 8;
            cp16(smA + (uint32_t)(r * AST + cc) * 2, As + (size_t)r * ldA + cc);
            cp16(smBh + (uint32_t)(r * AST + cc) * 2, Wh + (size_t)r * ldW + cc);
            if (NP == 2)
                cp16(smBl + (uint32_t)(r * AST + cc) * 2, Wl + (size_t)r * ldW + cc);
        }
        asm volatile("cp.async.commit_group;\n" ::: "memory");
    };

    const int arow = wm * 32 + ((lane >> 3) & 1) * 8 + (lane & 7);
    const int akof = ((lane >> 4) & 1) * 8;
    const int brow = wn * 64 + ((lane >> 4) & 1) * 8 + (lane & 7);
    const int bkof = ((lane >> 3) & 1) * 8;

    issue_load(0, 0);
    if (nch > 1) issue_load(1, 1);

    for (int i = 0; i < nch; i++) {
        if (i == nch - 1) asm volatile("cp.async.wait_group 0;\n" ::: "memory");
        else              asm volatile("cp.async.wait_group 1;\n" ::: "memory");
        __syncthreads();
        if (i + 2 < nch) issue_load(i + 2, (i + 2) % NSTAGE);

        uint32_t smA = base + (i % NSTAGE) * (3 * STG);
        uint32_t smBh = smA + STG;
        #pragma unroll
        for (int kk = 0; kk < 2; kk++) {
            const int k0 = kk * 16;
            uint32_t a[2][4];
            #pragma unroll
            for (int fm = 0; fm < 2; fm++)
                ldsm4(a[fm][0], a[fm][1], a[fm][2], a[fm][3],
                      smA + (uint32_t)((arow + fm * 16) * AST + k0 + akof) * 2);
            #pragma unroll
            for (int p = 0; p < NP; p++) {
                uint32_t wb = smBh + p * STG;
                #pragma unroll
                for (int fb = 0; fb < 4; fb++) {
                    uint32_t b0, b1, b2, b3;
                    ldsm4(b0, b1, b2, b3,
                          wb + (uint32_t)((brow + fb * 16) * AST + k0 + bkof) * 2);
                    #pragma unroll
                    for (int fm = 0; fm < 2; fm++) {
                        mma16816h(acc[fm][2 * fb],     a[fm], b0, b1);
                        mma16816h(acc[fm][2 * fb + 1], a[fm], b2, b3);
                    }
                }
            }
        }
        __syncthreads();
    }

    const int lr = lane >> 2, lc = (lane & 3) * 2;
    #pragma unroll
    for (int fm = 0; fm < 2; fm++) {
        #pragma unroll
        for (int fn = 0; fn < 8; fn++) {
            float* cc = acc[fm][fn];
            int m0 = bm + wm * 32 + fm * 16 + lr;
            int n0 = bn + wn * 64 + fn * 8 + lc;
            float b0 = bias[n0], b1 = bias[n0 + 1];
            float v00 = cc[0] + b0, v01 = cc[1] + b1;
            float v10 = cc[2] + b0, v11 = cc[3] + b1;
            if (EPI == 2) {
                float2 r0 = *(const float2*)&C[(size_t)m0 * N + n0];
                float2 r1 = *(const float2*)&C[(size_t)(m0 + 8) * N + n0];
                *(float2*)&C[(size_t)m0 * N + n0]       = make_float2(v00 + r0.x, v01 + r0.y);
                *(float2*)&C[(size_t)(m0 + 8) * N + n0] = make_float2(v10 + r1.x, v11 + r1.y);
            } else {
                *(half2*)&Ch[(size_t)m0 * N + n0]       = __floats2half2_rn(v00, v01);
                *(half2*)&Ch[(size_t)(m0 + 8) * N + n0] = __floats2half2_rn(v10, v11);
            }
        }
    }
}

// ---- 64x128 tile, 256 threads (8 warps, 2m x 4n), fused dual-W ----
#define ASTGH (64 * AST * 2)           // 5120
#define BSTGH (128 * AST * 2)          // 10240
#define HSTG (ASTGH + 2 * BSTGH)       // 25600
#define NSTAGE_H 3
#define GSMH (NSTAGE_H * HSTG)         // 76800

template<int EPI, int NP>
__global__ __launch_bounds__(256)
void gemm_h16(const __half* __restrict__ A, int ldA,
              const __half* __restrict__ W, int ldW,
              const float* __restrict__ bias,
              float* __restrict__ C, __half* __restrict__ Ch, int N, int K)
{
    extern __shared__ __align__(256) char smraw[];
    const uint32_t base = smem_u32(smraw);
    const int tid = threadIdx.x;
    const int bm = blockIdx.y * 64, bn = blockIdx.x * 128;
    const int lane = tid & 31, warp = tid >> 5;
    const int wm = warp & 1, wn = warp >> 1;       // 2 x 4
    const int nch = K / BK;

    float acc[2][4][4];
    #pragma unroll
    for (int i = 0; i < 2; i++)
        #pragma unroll
        for (int j = 0; j < 4; j++)
            #pragma unroll
            for (int k = 0; k < 4; k++) acc[i][j][k] = 0.f;

    auto issue_load = [&](int kc, int st) {
        uint32_t smA = base + st * HSTG;
        uint32_t smBh = smA + ASTGH;
        uint32_t smBl = smBh + BSTGH;
        const __half* As = A + (size_t)bm * ldA + kc * BK;
        const __half* Wh = W + (size_t)bn * ldW + kc * BK;
        const __half* Wl = Wh + K;
        {
            int r = tid >> 2, cc = (tid & 3) * 8;
            cp16(smA + (uint32_t)(r * AST + cc) * 2, As + (size_t)r * ldA + cc);
        }
        #pragma unroll
        for (int j = 0; j < 2; j++) {
            int u = j * 256 + tid;
            int r = u >> 2, cc = (u & 3) * 8;
            cp16(smBh + (uint32_t)(r * AST + cc) * 2, Wh + (size_t)r * ldW + cc);
            if (NP == 2)
                cp16(smBl + (uint32_t)(r * AST + cc) * 2, Wl + (size_t)r * ldW + cc);
        }
        asm volatile("cp.async.commit_group;\n" ::: "memory");
    };

    const int arow = wm * 32 + ((lane >> 3) & 1) * 8 + (lane & 7);
    const int akof = ((lane >> 4) & 1) * 8;
    const int brow = wn * 32 + ((lane >> 4) & 1) * 8 + (lane & 7);
    const int bkof = ((lane >> 3) & 1) * 8;

    issue_load(0, 0);
    if (nch > 1) issue_load(1, 1);

    for (int i = 0; i < nch; i++) {
        if (i == nch - 1) asm volatile("cp.async.wait_group 0;\n" ::: "memory");
        else              asm volatile("cp.async.wait_group 1;\n" ::: "memory");
        __syncthreads();
        if (i + 2 < nch) issue_load(i + 2, (i + 2) % NSTAGE_H);

        uint32_t smA = base + (i % NSTAGE_H) * HSTG;
        uint32_t smBh = smA + ASTGH;
        #pragma unroll
        for (int kk = 0; kk < 2; kk++) {
            const int k0 = kk * 16;
            uint32_t a[2][4];
            #pragma unroll
            for (int fm = 0; fm < 2; fm++)
                ldsm4(a[fm][0], a[fm][1], a[fm][2], a[fm][3],
                      smA + (uint32_t)((arow + fm * 16) * AST + k0 + akof) * 2);
            #pragma unroll
            for (int p = 0; p < NP; p++) {
                uint32_t wb = smBh + p * BSTGH;
                #pragma unroll
                for (int g = 0; g < 2; g++) {
                    uint32_t b0, b1, b2, b3;
                    ldsm4(b0, b1, b2, b3,
                          wb + (uint32_t)((brow + g * 16) * AST + k0 + bkof) * 2);
                    #pragma unroll
                    for (int fm = 0; fm < 2; fm++) {
                        mma16816h(acc[fm][2 * g],     a[fm], b0, b1);
                        mma16816h(acc[fm][2 * g + 1], a[fm], b2, b3);
                    }
                }
            }
        }
        __syncthreads();
    }

    const int lr = lane >> 2, lc = (lane & 3) * 2;
    #pragma unroll
    for (int fm = 0; fm < 2; fm++) {
        #pragma unroll
        for (int fn = 0; fn < 4; fn++) {
            float* cc = acc[fm][fn];
            int m0 = bm + wm * 32 + fm * 16 + lr;
            int n0 = bn + wn * 32 + fn * 8 + lc;
            float b0 = bias[n0], b1 = bias[n0 + 1];
            float v00 = cc[0] + b0, v01 = cc[1] + b1;
            float v10 = cc[2] + b0, v11 = cc[3] + b1;
            if (EPI == 1) {
                v00 = 0.5f * v00 * (1.0f + erff(v00 * 0.70710678118654752f));
                v01 = 0.5f * v01 * (1.0f + erff(v01 * 0.70710678118654752f));
                v10 = 0.5f * v10 * (1.0f + erff(v10 * 0.70710678118654752f));
                v11 = 0.5f * v11 * (1.0f + erff(v11 * 0.70710678118654752f));
            }
            if (EPI == 2) {
                float2 r0 = *(const float2*)&C[(size_t)m0 * N + n0];
                float2 r1 = *(const float2*)&C[(size_t)(m0 + 8) * N + n0];
                *(float2*)&C[(size_t)m0 * N + n0]       = make_float2(v00 + r0.x, v01 + r0.y);
                *(float2*)&C[(size_t)(m0 + 8) * N + n0] = make_float2(v10 + r1.x, v11 + r1.y);
            } else {
                *(half2*)&Ch[(size_t)m0 * N + n0]       = __floats2half2_rn(v00, v01);
                *(half2*)&Ch[(size_t)(m0 + 8) * N + n0] = __floats2half2_rn(v10, v11);
            }
        }
    }
}

// ---- bf16-split 3-pass GEMM (64x128, 128 threads), fp16 hi|lo out — weight fold ----
#define FSTGH (ASTGH + BSTGH)
#define GSMF (NSTAGE_H * FSTGH)

__global__ __launch_bounds__(128)
void gemm_bf(const __nv_bfloat16* __restrict__ A2, int ldA,
             const __nv_bfloat16* __restrict__ W2, int ldW,
             const float* __restrict__ bias,
             __half* __restrict__ C3, int N, int K)
{
    extern __shared__ __align__(256) char smraw[];
    const uint32_t base = smem_u32(smraw);
    const int tid = threadIdx.x;
    const int bm = blockIdx.y * 64, bn = blockIdx.x * 128;
    const int lane = tid & 31, warp = tid >> 5;
    const int wm = warp & 1, wn = warp >> 1;       // 2 x 2, warp tile 32x64
    const int nkc = K / BK;
    const int nch = 3 * nkc;

    float acc[2][8][4];
    #pragma unroll
    for (int i = 0; i < 2; i++)
        #pragma unroll
        for (int j = 0; j < 8; j++)
            #pragma unroll
            for (int k = 0; k < 4; k++) acc[i][j][k] = 0.f;

    auto issue_load = [&](int i, int st) {
        int s = i / nkc, kc = i - s * nkc;
        int ao = ((s == 2) ? K : 0) + kc * BK;
        int wo = ((s == 1) ? K : 0) + kc * BK;
        uint32_t smA = base + st * FSTGH;
        uint32_t smB = smA + ASTGH;
        const __nv_bfloat16* As = A2 + (size_t)bm * ldA + ao;
        const __nv_bfloat16* Ws = W2 + (size_t)bn * ldW + wo;
        #pragma unroll
        for (int j = 0; j < 2; j++) {
            int u = j * 128 + tid;
            int r = u >> 2, cc = (u & 3) * 8;
            cp16(smA + (uint32_t)(r * AST + cc) * 2, As + (size_t)r * ldA + cc);
        }
        #pragma unroll
        for (int j = 0; j < 4; j++) {
            int u = j * 128 + tid;
            int r = u >> 2, cc = (u & 3) * 8;
            cp16(smB + (uint32_t)(r * AST + cc) * 2, Ws + (size_t)r * ldW + cc);
        }
        asm volatile("cp.async.commit_group;\n" ::: "memory");
    };

    const int arow = wm * 32 + ((lane >> 3) & 1) * 8 + (lane & 7);
    const int akof = ((lane >> 4) & 1) * 8;
    const int brow = wn * 64 + ((lane >> 4) & 1) * 8 + (lane & 7);
    const int bkof = ((lane >> 3) & 1) * 8;

    issue_load(0, 0);
    if (nch > 1) issue_load(1, 1);

    for (int i = 0; i < nch; i++) {
        if (i == nch - 1) asm volatile("cp.async.wait_group 0;\n" ::: "memory");
        else              asm volatile("cp.async.wait_group 1;\n" ::: "memory");
        __syncthreads();
        if (i + 2 < nch) issue_load(i + 2, (i + 2) % NSTAGE_H);

        uint32_t smA = base + (i % NSTAGE_H) * FSTGH;
        uint32_t smB = smA + ASTGH;
        #pragma unroll
        for (int kk = 0; kk < 2; kk++) {
            const int k0 = kk * 16;
            uint32_t a[2][4];
            #pragma unroll
            for (int fm = 0; fm < 2; fm++)
                ldsm4(a[fm][0], a[fm][1], a[fm][2], a[fm][3],
                      smA + (uint32_t)((arow + fm * 16) * AST + k0 + akof) * 2);
            #pragma unroll
            for (int fb = 0; fb < 4; fb++) {
                uint32_t b0, b1, b2, b3;
                ldsm4(b0, b1, b2, b3,
                      smB + (uint32_t)((brow + fb * 16) * AST + k0 + bkof) * 2);
                #pragma unroll
                for (int fm = 0; fm < 2; fm++) {
                    mma16816(acc[fm][2 * fb],     a[fm], b0, b1);
                    mma16816(acc[fm][2 * fb + 1], a[fm], b2, b3);
                }
            }
        }
        __syncthreads();
    }

    const int lr = lane >> 2, lc = (lane & 3) * 2;
    #pragma unroll
    for (int fm = 0; fm < 2; fm++) {
        #pragma unroll
        for (int fn = 0; fn < 8; fn++) {
            float* cc = acc[fm][fn];
            int m0 = bm + wm * 32 + fm * 16 + lr;
            int n0 = bn + wn * 64 + fn * 8 + lc;
            float b0 = bias[n0], b1 = bias[n0 + 1];
            #pragma unroll
            for (int rr = 0; rr < 2; rr++) {
                float va = cc[rr * 2] + b0, vb = cc[rr * 2 + 1] + b1;
                __half ha = __float2half(va), hb = __float2half(vb);
                __half la = __float2half(va - __half2float(ha));
                __half lb = __float2half(vb - __half2float(hb));
                size_t row = (size_t)(m0 + rr * 8) * 2 * N;
                *(half2*)&C3[row + n0]     = half2(ha, hb);
                *(half2*)&C3[row + N + n0] = half2(la, lb);
            }
        }
    }
}

// ================= fused flash attention (fp16, BQ=128, 256 threads) =================
#define BQ 128
#define BKC 64
#define QST 72
#define FTILEQ (128 * QST * 2)
#define FTILE (64 * QST * 2)
#define FSTG (2 * FTILE)
#define FA_SMEM (FTILEQ + 2 * FSTG + 64)

__global__ __launch_bounds__(256)
void fattn(const __half* __restrict__ Qp, int ldq,
           const __half* __restrict__ Kp, int ldk,
           const __half* __restrict__ Vh, int ldv,
           const __half* __restrict__ pm, __half* __restrict__ Oh, int Tk)
{
    extern __shared__ __align__(256) char smraw[];
    const uint32_t base = smem_u32(smraw);
    const int tid = threadIdx.x, lane = tid & 31, warp = tid >> 5;
    const int bh = (int)blockIdx.y, b = bh >> 3, h = bh & 7;
    const int q0 = (int)blockIdx.x * BQ;

    const __half* Qb = Qp + (size_t)(b * LQ + q0) * ldq + h * HD;
    const __half* Kb = Kp + (size_t)b * Tk * ldk + h * HD;
    const __half* Vb = Vh + (size_t)b * Tk * ldv + h * HD;

    // Q tile (128 rows)
    #pragma unroll
    for (int j = 0; j < 4; j++) {
        int u = j * 256 + tid, r = u >> 3, c8 = (u & 7) * 8;
        cp16(base + (uint32_t)(r * QST + c8) * 2, Qb + (size_t)r * ldq + c8);
    }
    asm volatile("cp.async.commit_group;\n" ::: "memory");

    // ones columns (64..71) in both stages' V tiles
    if (tid < 128) {
        int r = tid >> 1, cq = (tid & 1) * 4;
        #pragma unroll
        for (int st = 0; st < 2; st++) {
            size_t off = (size_t)FTILEQ + (size_t)st * FSTG + FTILE
                       + (size_t)(r * QST + 64 + cq) * 2;
            *(uint2*)(smraw + off) = make_uint2(0x3C003C00u, 0x3C003C00u);
        }
    }

    const int nc = Tk / BKC;
    auto load_chunk = [&](int ci, int st) {
        uint32_t sb = base + FTILEQ + st * FSTG;
        const __half* Kc = Kb + (size_t)ci * BKC * ldk;
        const __half* Vc = Vb + (size_t)ci * BKC * ldv;
        #pragma unroll
        for (int j = 0; j < 2; j++) {
            int u = j * 256 + tid, r = u >> 3, c8 = (u & 7) * 8;
            uint32_t off = (uint32_t)(r * QST + c8) * 2;
            cp16(sb + off,         Kc + (size_t)r * ldk + c8);
            cp16(sb + FTILE + off, Vc + (size_t)r * ldv + c8);
        }
        asm volatile("cp.async.commit_group;\n" ::: "memory");
    };

    load_chunk(0, 0);
    asm volatile("cp.async.wait_group 1;\n" ::: "memory");
    __syncthreads();

    const int qrow = warp * 16 + ((lane >> 3) & 1) * 8 + (lane & 7);
    const int qko  = ((lane >> 4) & 1) * 8;
    uint32_t qf[4][4];
    #pragma unroll
    for (int ds = 0; ds < 4; ds++)
        ldsm4(qf[ds][0], qf[ds][1], qf[ds][2], qf[ds][3],
              base + (uint32_t)(qrow * QST + ds * 16 + qko) * 2);

    load_chunk(1, 1);

    float o[8][4], osum[4];
    #pragma unroll
    for (int i = 0; i < 8; i++)
        #pragma unroll
        for (int j = 0; j < 4; j++) o[i][j] = 0.f;
    #pragma unroll
    for (int j = 0; j < 4; j++) osum[j] = 0.f;

    const float SC  = 0.125f * 1.44269504088896f;
    const float L2E = 1.44269504088896f;
    const int lr = lane >> 2, lc = (lane & 3) * 2;
    const int krow = ((lane >> 4) & 1) * 8 + (lane & 7);
    const int kko  = ((lane >> 3) & 1) * 8;
    const int vrow = lane & 15;
    const int vco  = ((lane >> 4) & 1) * 8;
    const int qr_g = q0 + warp * 16 + lr;

    for (int ci = 0; ci < nc; ci++) {
        if (ci == nc - 1) asm volatile("cp.async.wait_group 0;\n" ::: "memory");
        else              asm volatile("cp.async.wait_group 1;\n" ::: "memory");
        __syncthreads();

        uint32_t sb = base + FTILEQ + (ci & 1) * FSTG;

        // ---- S = Q·K^T ----
        float s[8][4];
        #pragma unroll
        for (int i = 0; i < 8; i++)
            #pragma unroll
            for (int j = 0; j < 4; j++) s[i][j] = 0.f;
        #pragma unroll
        for (int ds = 0; ds < 4; ds++) {
            #pragma unroll
            for (int g = 0; g < 4; g++) {
                uint32_t b0, b1, b2, b3;
                ldsm4(b0, b1, b2, b3,
                      sb + (uint32_t)((g * 16 + krow) * QST + ds * 16 + kko) * 2);
                mma16816h(s[2 * g],     qf[ds], b0, b1);
                mma16816h(s[2 * g + 1], qf[ds], b2, b3);
            }
        }

        // ---- probs as fp16 fragments ----
        uint32_t ph[4][4];
        #pragma unroll
        for (int nt = 0; nt < 8; nt++) {
            float t0 = s[nt][0] * SC, t1 = s[nt][1] * SC;
            float t2 = s[nt][2] * SC, t3 = s[nt][3] * SC;
            if (pm) {
                const __half* pmr = pm + (size_t)qr_g * Tk + ci * BKC + nt * 8 + lc;
                float2 m0 = __half22float2(*(const half2*)pmr);
                float2 m1 = __half22float2(*(const half2*)(pmr + (size_t)8 * Tk));
                t0 = fmaf(m0.x, L2E, t0); t1 = fmaf(m0.y, L2E, t1);
                t2 = fmaf(m1.x, L2E, t2); t3 = fmaf(m1.y, L2E, t3);
            }
            int j = nt >> 1, qi = (nt & 1) * 2;
            ph[j][qi]     = packex2h2(t0, t1);
            ph[j][qi + 1] = packex2h2(t2, t3);
        }

        // ---- O += P·V + row sums via ones columns ----
        uint32_t vb = sb + FTILE;
        #pragma unroll
        for (int ks = 0; ks < 4; ks++) {
            const uint32_t* pf = ph[ks];
            #pragma unroll
            for (int g = 0; g < 4; g++) {
                uint32_t b0, b1, b2, b3;
                ldsm4t(b0, b1, b2, b3,
                       vb + (uint32_t)((ks * 16 + vrow) * QST + g * 16 + vco) * 2);
                mma16816h(o[2 * g],     pf, b0, b1);
                mma16816h(o[2 * g + 1], pf, b2, b3);
            }
            {
                uint32_t b0, b1, b2, b3;
                ldsm4t(b0, b1, b2, b3,
                       vb + (uint32_t)((ks * 16 + vrow) * QST + 64 + vco) * 2);
                mma16816h(osum, pf, b0, b1);
            }
        }

        __syncthreads();
        if (ci + 2 < nc) load_chunk(ci + 2, ci & 1);
    }

    float inv0 = 1.0f / osum[0], inv1 = 1.0f / osum[2];

    const size_t row0 = (size_t)(b * LQ + qr_g);
    #pragma unroll
    for (int nt = 0; nt < 8; nt++) {
        int col = h * HD + nt * 8 + lc;
        *(half2*)&Oh[row0 * D + col] =
            __floats2half2_rn(o[nt][0] * inv0, o[nt][1] * inv0);
        *(half2*)&Oh[(row0 + 8) * D + col] =
            __floats2half2_rn(o[nt][2] * inv1, o[nt][3] * inv1);
    }
}

// ---------------- elementwise: fp32 [rows,K] -> fp16 [rows,2K] hi|lo ----------------
__global__ void hsplit(const float* __restrict__ src, __half* __restrict__ dst, int K)
{
    int c = blockIdx.x * 256 + threadIdx.x;
    int r = blockIdx.y;
    float x = src[(size_t)r * K + c];
    __half h = __float2half(x);
    __half l = __float2half(x - __half2float(h));
    dst[(size_t)r * 2 * K + c] = h;
    dst[(size_t)r * 2 * K + K + c] = l;
}

__global__ void hconv(const float* __restrict__ src, __half* __restrict__ dst)
{
    size_t i = (size_t)blockIdx.x * 256 + threadIdx.x;
    dst[i] = __float2half(src[i]);
}

// split KV rows of xw_qkv -> g_wkv2 (per block: rows D..3D), bf16 hi|lo
__global__ void split_kv(const float* __restrict__ xw_qkv, __nv_bfloat16* __restrict__ dst)
{
    int c = blockIdx.x * 256 + threadIdx.x;
    int g = blockIdx.y;
    int i = g / (2 * D), r = g % (2 * D);
    float x = xw_qkv[((size_t)i * 3 * D + D + r) * D + c];
    __nv_bfloat16 h, l; split2(x, h, l);
    dst[(size_t)g * 2 * D + c] = h;
    dst[(size_t)g * 2 * D + D + c] = l;
}

// transpose+split: proj_w[D, D_IN] -> wT2[D_IN, 2*D]
__global__ void tsplit_proj(const float* __restrict__ pw, __nv_bfloat16* __restrict__ wT2)
{
    int k = blockIdx.x * 256 + threadIdx.x;
    int c = blockIdx.y;
    float x = pw[(size_t)k * D_IN + c];
    __nv_bfloat16 h, l; split2(x, h, l);
    wT2[(size_t)c * 2 * D + k] = h;
    wT2[(size_t)c * 2 * D + D + k] = l;
}

// folded KV bias for [Kall | Vall] layout
__global__ void kvbias_kernel(const float* __restrict__ xw_qkv, const float* __restrict__ xb_qkv,
                              const float* __restrict__ proj_b, float* __restrict__ bc)
{
    __shared__ float sh[32];
    int g = blockIdx.x;
    int wrow;
    if (g < 3072) { int i = g >> 9, n = g & 511; wrow = i * 3 * D + D + n; }
    else          { int gg = g - 3072; int i = gg >> 9, n = gg & 511; wrow = i * 3 * D + 2 * D + n; }
    const float* wr = xw_qkv + (size_t)wrow * D;
    float s = 0.f;
    for (int k = threadIdx.x; k < D; k += 256) s += wr[k] * proj_b[k];
    float tot = block_sum256(s, sh);
    if (threadIdx.x == 0) bc[g] = tot + xb_qkv[wrow];
}

// ---------------- LayerNorm -> fp16 ----------------
__global__ void ln_half(const float* __restrict__ x, const float* __restrict__ g,
                        const float* __restrict__ b, __half* __restrict__ y)
{
    __shared__ float sh[32];
    const int row = blockIdx.x, tid = threadIdx.x;
    const float* xr = x + (size_t)row * D;
    float2 v = *(const float2*)&xr[tid * 2];
    float total = block_sum256(v.x + v.y, sh);
    float mean = total * (1.0f / D);
    float d0 = v.x - mean, d1 = v.y - mean;
    float sq = block_sum256(d0 * d0 + d1 * d1, sh);
    float inv = rsqrtf(sq * (1.0f / D) + 1e-5f);
    float2 go = *(const float2*)&g[tid * 2];
    float2 bo = *(const float2*)&b[tid * 2];
    ((half2*)(y + (size_t)row * D))[tid] =
        __floats2half2_rn(d0 * inv * go.x + bo.x, d1 * inv * go.y + bo.y);
}

// ---------------- plain LayerNorm (final) ----------------
__global__ void ln_kernel(const float* __restrict__ x, const float* __restrict__ g,
                          const float* __restrict__ b, float* __restrict__ y)
{
    __shared__ float sh[32];
    const int row = blockIdx.x, tid = threadIdx.x;
    const float* xr = x + (size_t)row * D;
    float2 v = *(const float2*)&xr[tid * 2];
    float total = block_sum256(v.x + v.y, sh);
    float mean = total * (1.0f / D);
    float d0 = v.x - mean, d1 = v.y - mean;
    float sq = block_sum256(d0 * d0 + d1 * d1, sh);
    float inv = rsqrtf(sq * (1.0f / D) + 1e-5f);
    float2 go = *(const float2*)&g[tid * 2];
    float2 bo = *(const float2*)&b[tid * 2];
    float2 o;
    o.x = d0 * inv * go.x + bo.x;
    o.y = d1 * inv * go.y + bo.y;
    *(float2*)&y[(size_t)row * D + tid * 2] = o;
}

// ---------------- all 6 relative-time masks (fp16 out) ----------------
__global__ void mask6_kernel(const float* __restrict__ rel_bias, const float* __restrict__ ms,
                             __half* __restrict__ pm6)
{
    int k = blockIdx.x * 256 + threadIdx.x;
    int q = blockIdx.y;
    int z = blockIdx.z;
    float tau = (float)q * (4095.0f / 255.0f);
    float dt = (float)k - tau;
    float c = fminf(fmaxf(dt, -128.f), 128.f);
    int idx = (int)c + 128;
    float zz = dt * (1.0f / 32.0f);
    float lg = logf(expf(-0.5f * zz * zz) + 1e-6f);
    pm6[(size_t)z * LQ * T + (size_t)q * T + k] =
        __float2half(ms[z] * (rel_bias[z * 257 + idx] + lg));
}

// ---------------- misc ----------------
__global__ void bcast_latents(const float* __restrict__ src, float* __restrict__ dst)
{
    int i = blockIdx.x * 256 + threadIdx.x;
    dst[i] = src[i % (LQ * D)];
}

__global__ void mean_kernel(const float* __restrict__ x, float* __restrict__ out)
{
    int i = blockIdx.x * 256 + threadIdx.x;
    int b = i / D, d = i % D;
    float s = 0.f;
    for (int q = 0; q < LQ; q++) s += x[((size_t)b * LQ + q) * D + d];
    out[i] = s * (1.0f / LQ);
}

// ---------------- host orchestration ----------------
extern "C" void kernel_launch(void* const* d_in, const int* in_sizes, int n_in,
                              void* d_out, int out_size)
{
    (void)in_sizes; (void)n_in; (void)out_size;
    const float* tokens     = (const float*)d_in[0];
    const float* proj_w     = (const float*)d_in[1];
    const float* proj_b     = (const float*)d_in[2];
    const float* latents    = (const float*)d_in[3];
    const float* lnx_g      = (const float*)d_in[4];
    const float* lnx_b      = (const float*)d_in[5];
    const float* xw_qkv     = (const float*)d_in[6];
    const float* xb_qkv     = (const float*)d_in[7];
    const float* xw_o       = (const float*)d_in[8];
    const float* xb_o       = (const float*)d_in[9];
    const float* rel_bias   = (const float*)d_in[10];
    const float* mask_scale = (const float*)d_in[11];
    const float* mx_w1      = (const float*)d_in[12];
    const float* mx_b1      = (const float*)d_in[13];
    const float* mx_w2      = (const float*)d_in[14];
    const float* mx_b2      = (const float*)d_in[15];
    const float* lns_g      = (const float*)d_in[16];
    const float* lns_b      = (const float*)d_in[17];
    const float* sw_qkv     = (const float*)d_in[18];
    const float* sb_qkv     = (const float*)d_in[19];
    const float* sw_o       = (const float*)d_in[20];
    const float* sb_o       = (const float*)d_in[21];
    const float* ms_w1      = (const float*)d_in[22];
    const float* ms_b1      = (const float*)d_in[23];
    const float* ms_w2      = (const float*)d_in[24];
    const float* ms_b2      = (const float*)d_in[25];
    const float* lno_g      = (const float*)d_in[26];
    const float* lno_b      = (const float*)d_in[27];
    float* out = (float*)d_out;

    cudaFuncSetAttribute(gemm_b16<0, 1>, cudaFuncAttributeMaxDynamicSharedMemorySize, GSM);
    cudaFuncSetAttribute(gemm_b16<0, 2>, cudaFuncAttributeMaxDynamicSharedMemorySize, GSM);
    cudaFuncSetAttribute(gemm_h16<0, 2>, cudaFuncAttributeMaxDynamicSharedMemorySize, GSMH);
    cudaFuncSetAttribute(gemm_h16<1, 2>, cudaFuncAttributeMaxDynamicSharedMemorySize, GSMH);
    cudaFuncSetAttribute(gemm_h16<2, 2>, cudaFuncAttributeMaxDynamicSharedMemorySize, GSMH);
    cudaFuncSetAttribute(gemm_bf,        cudaFuncAttributeMaxDynamicSharedMemorySize, GSMF);
    cudaFuncSetAttribute(fattn,          cudaFuncAttributeMaxDynamicSharedMemorySize, FA_SMEM);

    float *plat, *ptmpf, *pbc, *pzb;
    __half *pmask6, *ptokh, *ptmph, *phidh, *path, *pqh, *pkallh, *pvallh, *psqh, *pwch,
           *pwxqkvh, *pwxoh, *pwmx1h, *pwmx2h, *pwsqkvh, *pwsoh, *pwms1h, *pwms2h;
    __nv_bfloat16 *pwkv2, *pwpT2;
    cudaGetSymbolAddress((void**)&plat,    g_lat);
    cudaGetSymbolAddress((void**)&ptmpf,   g_tmpf);
    cudaGetSymbolAddress((void**)&pmask6,  g_mask6);
    cudaGetSymbolAddress((void**)&pbc,     g_bc);
    cudaGetSymbolAddress((void**)&pzb,     g_zerob);
    cudaGetSymbolAddress((void**)&ptokh,   g_tokh);
    cudaGetSymbolAddress((void**)&ptmph,   g_tmph);
    cudaGetSymbolAddress((void**)&phidh,   g_hidh);
    cudaGetSymbolAddress((void**)&path,    g_ath);
    cudaGetSymbolAddress((void**)&pqh,     g_qh);
    cudaGetSymbolAddress((void**)&pkallh,  g_kallh);
    cudaGetSymbolAddress((void**)&pvallh,  g_vallh);
    cudaGetSymbolAddress((void**)&psqh,    g_sqh);
    cudaGetSymbolAddress((void**)&pwch,    g_wch);
    cudaGetSymbolAddress((void**)&pwxqkvh, g_wxqkvh);
    cudaGetSymbolAddress((void**)&pwxoh,   g_wxoh);
    cudaGetSymbolAddress((void**)&pwmx1h,  g_wmx1h);
    cudaGetSymbolAddress((void**)&pwmx2h,  g_wmx2h);
    cudaGetSymbolAddress((void**)&pwsqkvh, g_wsqkvh);
    cudaGetSymbolAddress((void**)&pwsoh,   g_wsoh);
    cudaGetSymbolAddress((void**)&pwms1h,  g_wms1h);
    cudaGetSymbolAddress((void**)&pwms2h,  g_wms2h);
    cudaGetSymbolAddress((void**)&pwkv2,   g_wkv2);
    cudaGetSymbolAddress((void**)&pwpT2,   g_wpT2);

    const int BT = B * T, BL = B * LQ;

    // ---- upfront: weight hi|lo splits, token convert ----
    hsplit<<<dim3(D / 256,   NB * 3 * D), 256>>>(xw_qkv, pwxqkvh, D);
    hsplit<<<dim3(D / 256,   NB * D),     256>>>(xw_o,   pwxoh,   D);
    hsplit<<<dim3(D / 256,   NB * HID),   256>>>(mx_w1,  pwmx1h,  D);
    hsplit<<<dim3(HID / 256, NB * D),     256>>>(mx_w2,  pwmx2h,  HID);
    hsplit<<<dim3(D / 256,   NB * 3 * D), 256>>>(sw_qkv, pwsqkvh, D);
    hsplit<<<dim3(D / 256,   NB * D),     256>>>(sw_o,   pwsoh,   D);
    hsplit<<<dim3(D / 256,   NB * HID),   256>>>(ms_w1,  pwms1h,  D);
    hsplit<<<dim3(HID / 256, NB * D),     256>>>(ms_w2,  pwms2h,  HID);
    hconv<<<(BT * D_IN) / 256, 256>>>(tokens, ptokh);

    // ---- fold (3-pass bf16 -> fp16 hi|lo): Wc = Wkv·Wp, layout [Kall | Vall] ----
    split_kv<<<dim3(D / 256, NB * 2 * D), 256>>>(xw_qkv, pwkv2);
    tsplit_proj<<<dim3(D / 256, D_IN), 256>>>(proj_w, pwpT2);
    for (int i = 0; i < NB; i++) {
        gemm_bf<<<dim3(D_IN / 128, 512 / 64), 128, GSMF>>>(
            pwkv2 + (size_t)(i * 2 * D) * 2 * D, 2 * D,
            pwpT2, 2 * D, pzb, pwch + (size_t)(i * 512) * 2 * D_IN, D_IN, D);
        gemm_bf<<<dim3(D_IN / 128, 512 / 64), 128, GSMF>>>(
            pwkv2 + (size_t)(i * 2 * D + 512) * 2 * D, 2 * D,
            pwpT2, 2 * D, pzb, pwch + (size_t)(3072 + i * 512) * 2 * D_IN, D_IN, D);
    }
    kvbias_kernel<<<KVN, 256>>>(xw_qkv, xb_qkv, proj_b, pbc);

    // ---- Kall (hi only) / Vall (fused dual-W), K=256 ----
    gemm_b16<0, 1><<<dim3(3072 / 128, BT / 128), 256, GSM>>>(
        ptokh, D_IN, pwch, 2 * D_IN, pbc, nullptr, pkallh, 3072, D_IN);
    gemm_b16<0, 2><<<dim3(3072 / 128, BT / 128), 256, GSM>>>(
        ptokh, D_IN, pwch + (size_t)3072 * 2 * D_IN, 2 * D_IN, pbc + 3072,
        nullptr, pvallh, 3072, D_IN);

    mask6_kernel<<<dim3(T / 256, LQ, NB), 256>>>(rel_bias, mask_scale, pmask6);
    bcast_latents<<<(BL * D) / 256, 256>>>(latents, plat);

    for (int i = 0; i < NB; i++) {
        // ---- cross attention ----
        ln_half<<<BL, 256>>>(plat, lnx_g + i * D, lnx_b + i * D, ptmph);
        gemm_h16<0, 2><<<dim3(D / 128, BL / 64), 256, GSMH>>>(
            ptmph, D, pwxqkvh + (size_t)i * 3 * D * 2 * D, 2 * D,
            xb_qkv + (size_t)i * 3 * D, nullptr, pqh, D, D);
        fattn<<<dim3(LQ / BQ, B * H), 256, FA_SMEM>>>(
            pqh, D,
            pkallh + (size_t)i * 512, 3072,
            pvallh + (size_t)i * 512, 3072,
            pmask6 + (size_t)i * LQ * T, path, T);
        gemm_h16<2, 2><<<dim3(D / 128, BL / 64), 256, GSMH>>>(
            path, D, pwxoh + (size_t)i * D * 2 * D, 2 * D, xb_o + i * D,
            plat, nullptr, D, D);

        // ---- cross MLP (pre-LN reuses lnx params) ----
        ln_half<<<BL, 256>>>(plat, lnx_g + i * D, lnx_b + i * D, ptmph);
        gemm_h16<1, 2><<<dim3(HID / 128, BL / 64), 256, GSMH>>>(
            ptmph, D, pwmx1h + (size_t)i * HID * 2 * D, 2 * D, mx_b1 + i * HID,
            nullptr, phidh, HID, D);
        gemm_h16<2, 2><<<dim3(D / 128, BL / 64), 256, GSMH>>>(
            phidh, HID, pwmx2h + (size_t)i * D * 2 * HID, 2 * HID, mx_b2 + i * D,
            plat, nullptr, D, HID);

        // ---- self attention ----
        ln_half<<<BL, 256>>>(plat, lns_g + i * D, lns_b + i * D, ptmph);
        gemm_h16<0, 2><<<dim3((3 * D) / 128, BL / 64), 256, GSMH>>>(
            ptmph, D, pwsqkvh + (size_t)i * 3 * D * 2 * D, 2 * D,
            sb_qkv + (size_t)i * 3 * D, nullptr, psqh, 3 * D, D);
        fattn<<<dim3(LQ / BQ, B * H), 256, FA_SMEM>>>(
            psqh, 3 * D,
            psqh + D, 3 * D,
            psqh + 2 * D, 3 * D,
            nullptr, path, LQ);
        gemm_h16<2, 2><<<dim3(D / 128, BL / 64), 256, GSMH>>>(
            path, D, pwsoh + (size_t)i * D * 2 * D, 2 * D, sb_o + i * D,
            plat, nullptr, D, D);

        // ---- self MLP ----
        ln_half<<<BL, 256>>>(plat, lns_g + i * D, lns_b + i * D, ptmph);
        gemm_h16<1, 2><<<dim3(HID / 128, BL / 64), 256, GSMH>>>(
            ptmph, D, pwms1h + (size_t)i * HID * 2 * D, 2 * D, ms_b1 + i * HID,
            nullptr, phidh, HID, D);
        gemm_h16<2, 2><<<dim3(D / 128, BL / 64), 256, GSMH>>>(
            phidh, HID, pwms2h + (size_t)i * D * 2 * HID, 2 * HID, ms_b2 + i * D,
            plat, nullptr, D, HID);
    }

    // final LN + mean over latents
    ln_kernel<<<BL, 256>>>(plat, lno_g, lno_b, ptmpf);
    mean_kernel<<<(B * D) / 256, 256>>>(ptmpf, out);
}

// round 15
// speedup vs baseline: 1.5068x; 1.2232x over previous
#include <cuda_runtime.h>
#include <cuda_bf16.h>
#include <cuda_fp16.h>
#include <cstdint>
#include <math.h>

// ---------------- problem constants ----------------
#define B   8
#define T   4096
#define D_IN 256
#define D   512
#define LQ  256
#define H   8
#define HD  64
#define NB  6
#define HID 2048
#define KVN (NB * 2 * D)

// ---------------- helpers ----------------
__device__ __forceinline__ uint32_t smem_u32(const void* p) {
    uint32_t a;
    asm("{ .reg .u64 t; cvta.to.shared.u64 t, %1; cvt.u32.u64 %0, t; }" : "=r"(a) : "l"(p));
    return a;
}
__device__ __forceinline__ void cp16(uint32_t dst, const void* src) {
    asm volatile("cp.async.cg.shared.global [%0], [%1], 16;\n" :: "r"(dst), "l"(src));
}
__device__ __forceinline__ void ldsm4(uint32_t& r0, uint32_t& r1, uint32_t& r2, uint32_t& r3,
                                      uint32_t addr) {
    asm volatile("ldmatrix.sync.aligned.m8n8.x4.shared.b16 {%0,%1,%2,%3}, [%4];"
        : "=r"(r0), "=r"(r1), "=r"(r2), "=r"(r3) : "r"(addr));
}
__device__ __forceinline__ void ldsm4t(uint32_t& r0, uint32_t& r1, uint32_t& r2, uint32_t& r3,
                                       uint32_t addr) {
    asm volatile("ldmatrix.sync.aligned.m8n8.x4.trans.shared.b16 {%0,%1,%2,%3}, [%4];"
        : "=r"(r0), "=r"(r1), "=r"(r2), "=r"(r3) : "r"(addr));
}
__device__ __forceinline__ void mma16816(float* c, const uint32_t* a, uint32_t b0, uint32_t b1) {
    asm volatile("mma.sync.aligned.m16n8k16.row.col.f32.bf16.bf16.f32 "
        "{%0,%1,%2,%3}, {%4,%5,%6,%7}, {%8,%9}, {%0,%1,%2,%3};"
        : "+f"(c[0]), "+f"(c[1]), "+f"(c[2]), "+f"(c[3])
        : "r"(a[0]), "r"(a[1]), "r"(a[2]), "r"(a[3]), "r"(b0), "r"(b1));
}
__device__ __forceinline__ void mma16816h(float* c, const uint32_t* a, uint32_t b0, uint32_t b1) {
    asm volatile("mma.sync.aligned.m16n8k16.row.col.f32.f16.f16.f32 "
        "{%0,%1,%2,%3}, {%4,%5,%6,%7}, {%8,%9}, {%0,%1,%2,%3};"
        : "+f"(c[0]), "+f"(c[1]), "+f"(c[2]), "+f"(c[3])
        : "r"(a[0]), "r"(a[1]), "r"(a[2]), "r"(a[3]), "r"(b0), "r"(b1));
}
__device__ __forceinline__ uint32_t packex2h2(float tlo, float thi) {
    uint32_t t, r;
    asm("cvt.rn.f16x2.f32 %0, %1, %2;" : "=r"(t) : "f"(thi), "f"(tlo));
    asm("ex2.approx.f16x2 %0, %1;" : "=r"(r) : "r"(t));
    return r;
}
__device__ __forceinline__ void split2(float x, __nv_bfloat16& h, __nv_bfloat16& l) {
    h = __float2bfloat16(x);
    l = __float2bfloat16(x - __bfloat162float(h));
}

// ---------------- scratch ----------------
__device__ float g_lat [B*LQ*D];
__device__ float g_tmpf[B*LQ*D];
__device__ float g_bc  [KVN];
__device__ float g_zerob[D_IN];

__device__ __align__(256) __half g_mask6[NB*LQ*T];
__device__ __align__(256) __half g_tokh [B*T*D_IN];
__device__ __align__(256) __half g_tmph [B*LQ*D];
__device__ __align__(256) __half g_hidh [B*LQ*HID];
__device__ __align__(256) __half g_ath  [B*LQ*D];
__device__ __align__(256) __half g_qh   [B*LQ*D];
__device__ __align__(256) __half g_kallh[(size_t)B*T*(NB*D)];
__device__ __align__(256) __half g_vallh[(size_t)B*T*(NB*D)];
__device__ __align__(256) __half g_sqh  [B*LQ*3*D];
// plain fp16 weights [N, K]
__device__ __align__(256) __half g_wch  [KVN*D_IN];
__device__ __align__(256) __half g_wxqkvh[NB*3*D*D];
__device__ __align__(256) __half g_wxoh  [NB*D*D];
__device__ __align__(256) __half g_wmx1h [NB*HID*D];
__device__ __align__(256) __half g_wmx2h [NB*D*HID];
__device__ __align__(256) __half g_wsqkvh[NB*3*D*D];
__device__ __align__(256) __half g_wsoh  [NB*D*D];
__device__ __align__(256) __half g_wms1h [NB*HID*D];
__device__ __align__(256) __half g_wms2h [NB*D*HID];
// bf16-split only for the weight-fold GEMM
__device__ __align__(256) __nv_bfloat16 g_wkv2[NB*2*D*2*D];
__device__ __align__(256) __nv_bfloat16 g_wpT2[D_IN*2*D];

// ---------------- reductions ----------------
__device__ __forceinline__ float block_sum256(float v, float* sh) {
    #pragma unroll
    for (int o = 16; o; o >>= 1) v += __shfl_xor_sync(0xffffffffu, v, o);
    if ((threadIdx.x & 31) == 0) sh[threadIdx.x >> 5] = v;
    __syncthreads();
    float t = (threadIdx.x < 8) ? sh[threadIdx.x] : 0.f;
    if (threadIdx.x < 32) {
        #pragma unroll
        for (int o = 4; o; o >>= 1) t += __shfl_xor_sync(0xffffffffu, t, o);
        if (threadIdx.x == 0) sh[0] = t;
    }
    __syncthreads();
    float r = sh[0];
    __syncthreads();
    return r;
}

// ================= fp16 single-pass GEMM: C = A·W^T + bias =================
#define BK 32
#define AST 40

// ---- 128x128 tile, 256 threads (KV production) ----
#define STG (128 * AST * 2)            // 10240
#define NSTAGE 3
#define GSM (NSTAGE * 2 * STG)         // 61440 -> 3 CTA/SM

template<int EPI>
__global__ __launch_bounds__(256)
void gemm_b16(const __half* __restrict__ A, int ldA,
              const __half* __restrict__ W, int ldW,
              const float* __restrict__ bias,
              float* __restrict__ C, __half* __restrict__ Ch, int N, int K)
{
    extern __shared__ __align__(256) char smraw[];
    const uint32_t base = smem_u32(smraw);
    const int tid = threadIdx.x;
    const int bm = blockIdx.y * 128, bn = blockIdx.x * 128;
    const int lane = tid & 31, warp = tid >> 5;
    const int wm = warp & 3, wn = warp >> 2;
    const int nch = K / BK;

    float acc[2][8][4];
    #pragma unroll
    for (int i = 0; i < 2; i++)
        #pragma unroll
        for (int j = 0; j < 8; j++)
            #pragma unroll
            for (int k = 0; k < 4; k++) acc[i][j][k] = 0.f;

    auto issue_load = [&](int kc, int st) {
        uint32_t smA = base + st * (2 * STG);
        uint32_t smB = smA + STG;
        const __half* As = A + (size_t)bm * ldA + kc * BK;
        const __half* Ws = W + (size_t)bn * ldW + kc * BK;
        #pragma unroll
        for (int j = 0; j < 2; j++) {
            int u = j * 256 + tid;
            int r = u >> 2, cc = (u & 3) * 8;
            cp16(smA + (uint32_t)(r * AST + cc) * 2, As + (size_t)r * ldA + cc);
            cp16(smB + (uint32_t)(r * AST + cc) * 2, Ws + (size_t)r * ldW + cc);
        }
        asm volatile("cp.async.commit_group;\n" ::: "memory");
    };

    const int arow = wm * 32 + ((lane >> 3) & 1) * 8 + (lane & 7);
    const int akof = ((lane >> 4) & 1) * 8;
    const int brow = wn * 64 + ((lane >> 4) & 1) * 8 + (lane & 7);
    const int bkof = ((lane >> 3) & 1) * 8;

    issue_load(0, 0);
    if (nch > 1) issue_load(1, 1);

    for (int i = 0; i < nch; i++) {
        if (i == nch - 1) asm volatile("cp.async.wait_group 0;\n" ::: "memory");
        else              asm volatile("cp.async.wait_group 1;\n" ::: "memory");
        __syncthreads();
        if (i + 2 < nch) issue_load(i + 2, (i + 2) % NSTAGE);

        uint32_t smA = base + (i % NSTAGE) * (2 * STG);
        uint32_t smB = smA + STG;
        #pragma unroll
        for (int kk = 0; kk < 2; kk++) {
            const int k0 = kk * 16;
            uint32_t a[2][4];
            #pragma unroll
            for (int fm = 0; fm < 2; fm++)
                ldsm4(a[fm][0], a[fm][1], a[fm][2], a[fm][3],
                      smA + (uint32_t)((arow + fm * 16) * AST + k0 + akof) * 2);
            #pragma unroll
            for (int fb = 0; fb < 4; fb++) {
                uint32_t b0, b1, b2, b3;
                ldsm4(b0, b1, b2, b3,
                      smB + (uint32_t)((brow + fb * 16) * AST + k0 + bkof) * 2);
                #pragma unroll
                for (int fm = 0; fm < 2; fm++) {
                    mma16816h(acc[fm][2 * fb],     a[fm], b0, b1);
                    mma16816h(acc[fm][2 * fb + 1], a[fm], b2, b3);
                }
            }
        }
        __syncthreads();
    }

    const int lr = lane >> 2, lc = (lane & 3) * 2;
    #pragma unroll
    for (int fm = 0; fm < 2; fm++) {
        #pragma unroll
        for (int fn = 0; fn < 8; fn++) {
            float* cc = acc[fm][fn];
            int m0 = bm + wm * 32 + fm * 16 + lr;
            int n0 = bn + wn * 64 + fn * 8 + lc;
            float b0 = bias[n0], b1 = bias[n0 + 1];
            float v00 = cc[0] + b0, v01 = cc[1] + b1;
            float v10 = cc[2] + b0, v11 = cc[3] + b1;
            if (EPI == 2) {
                float2 r0 = *(const float2*)&C[(size_t)m0 * N + n0];
                float2 r1 = *(const float2*)&C[(size_t)(m0 + 8) * N + n0];
                *(float2*)&C[(size_t)m0 * N + n0]       = make_float2(v00 + r0.x, v01 + r0.y);
                *(float2*)&C[(size_t)(m0 + 8) * N + n0] = make_float2(v10 + r1.x, v11 + r1.y);
            } else {
                *(half2*)&Ch[(size_t)m0 * N + n0]       = __floats2half2_rn(v00, v01);
                *(half2*)&Ch[(size_t)(m0 + 8) * N + n0] = __floats2half2_rn(v10, v11);
            }
        }
    }
}

// ---- 64x128 tile, 256 threads (8 warps, 2m x 4n, warp tile 32x32) ----
#define ASTGH (64 * AST * 2)           // 5120
#define BSTGH (128 * AST * 2)          // 10240
#define HSTG (ASTGH + BSTGH)           // 15360
#define NSTAGE_H 3
#define GSMH (NSTAGE_H * HSTG)         // 46080 -> 4 CTA/SM

template<int EPI>
__global__ __launch_bounds__(256)
void gemm_h16(const __half* __restrict__ A, int ldA,
              const __half* __restrict__ W, int ldW,
              const float* __restrict__ bias,
              float* __restrict__ C, __half* __restrict__ Ch, int N, int K)
{
    extern __shared__ __align__(256) char smraw[];
    const uint32_t base = smem_u32(smraw);
    const int tid = threadIdx.x;
    const int bm = blockIdx.y * 64, bn = blockIdx.x * 128;
    const int lane = tid & 31, warp = tid >> 5;
    const int wm = warp & 1, wn = warp >> 1;       // 2 x 4
    const int nch = K / BK;

    float acc[2][4][4];
    #pragma unroll
    for (int i = 0; i < 2; i++)
        #pragma unroll
        for (int j = 0; j < 4; j++)
            #pragma unroll
            for (int k = 0; k < 4; k++) acc[i][j][k] = 0.f;

    auto issue_load = [&](int kc, int st) {
        uint32_t smA = base + st * HSTG;
        uint32_t smB = smA + ASTGH;
        const __half* As = A + (size_t)bm * ldA + kc * BK;
        const __half* Ws = W + (size_t)bn * ldW + kc * BK;
        {
            int r = tid >> 2, cc = (tid & 3) * 8;
            cp16(smA + (uint32_t)(r * AST + cc) * 2, As + (size_t)r * ldA + cc);
        }
        #pragma unroll
        for (int j = 0; j < 2; j++) {
            int u = j * 256 + tid;
            int r = u >> 2, cc = (u & 3) * 8;
            cp16(smB + (uint32_t)(r * AST + cc) * 2, Ws + (size_t)r * ldW + cc);
        }
        asm volatile("cp.async.commit_group;\n" ::: "memory");
    };

    const int arow = wm * 32 + ((lane >> 3) & 1) * 8 + (lane & 7);
    const int akof = ((lane >> 4) & 1) * 8;
    const int brow = wn * 32 + ((lane >> 4) & 1) * 8 + (lane & 7);
    const int bkof = ((lane >> 3) & 1) * 8;

    issue_load(0, 0);
    if (nch > 1) issue_load(1, 1);

    for (int i = 0; i < nch; i++) {
        if (i == nch - 1) asm volatile("cp.async.wait_group 0;\n" ::: "memory");
        else              asm volatile("cp.async.wait_group 1;\n" ::: "memory");
        __syncthreads();
        if (i + 2 < nch) issue_load(i + 2, (i + 2) % NSTAGE_H);

        uint32_t smA = base + (i % NSTAGE_H) * HSTG;
        uint32_t smB = smA + ASTGH;
        #pragma unroll
        for (int kk = 0; kk < 2; kk++) {
            const int k0 = kk * 16;
            uint32_t a[2][4];
            #pragma unroll
            for (int fm = 0; fm < 2; fm++)
                ldsm4(a[fm][0], a[fm][1], a[fm][2], a[fm][3],
                      smA + (uint32_t)((arow + fm * 16) * AST + k0 + akof) * 2);
            #pragma unroll
            for (int g = 0; g < 2; g++) {
                uint32_t b0, b1, b2, b3;
                ldsm4(b0, b1, b2, b3,
                      smB + (uint32_t)((brow + g * 16) * AST + k0 + bkof) * 2);
                #pragma unroll
                for (int fm = 0; fm < 2; fm++) {
                    mma16816h(acc[fm][2 * g],     a[fm], b0, b1);
                    mma16816h(acc[fm][2 * g + 1], a[fm], b2, b3);
                }
            }
        }
        __syncthreads();
    }

    const int lr = lane >> 2, lc = (lane & 3) * 2;
    #pragma unroll
    for (int fm = 0; fm < 2; fm++) {
        #pragma unroll
        for (int fn = 0; fn < 4; fn++) {
            float* cc = acc[fm][fn];
            int m0 = bm + wm * 32 + fm * 16 + lr;
            int n0 = bn + wn * 32 + fn * 8 + lc;
            float b0 = bias[n0], b1 = bias[n0 + 1];
            float v00 = cc[0] + b0, v01 = cc[1] + b1;
            float v10 = cc[2] + b0, v11 = cc[3] + b1;
            if (EPI == 1) {
                v00 = 0.5f * v00 * (1.0f + erff(v00 * 0.70710678118654752f));
                v01 = 0.5f * v01 * (1.0f + erff(v01 * 0.70710678118654752f));
                v10 = 0.5f * v10 * (1.0f + erff(v10 * 0.70710678118654752f));
                v11 = 0.5f * v11 * (1.0f + erff(v11 * 0.70710678118654752f));
            }
            if (EPI == 2) {
                float2 r0 = *(const float2*)&C[(size_t)m0 * N + n0];
                float2 r1 = *(const float2*)&C[(size_t)(m0 + 8) * N + n0];
                *(float2*)&C[(size_t)m0 * N + n0]       = make_float2(v00 + r0.x, v01 + r0.y);
                *(float2*)&C[(size_t)(m0 + 8) * N + n0] = make_float2(v10 + r1.x, v11 + r1.y);
            } else {
                *(half2*)&Ch[(size_t)m0 * N + n0]       = __floats2half2_rn(v00, v01);
                *(half2*)&Ch[(size_t)(m0 + 8) * N + n0] = __floats2half2_rn(v10, v11);
            }
        }
    }
}

// ---- bf16-split 3-pass GEMM (64x128, 128 threads), plain fp16 out — weight fold ----
#define FSTGH (ASTGH + BSTGH)
#define GSMF (NSTAGE_H * FSTGH)

__global__ __launch_bounds__(128)
void gemm_bf(const __nv_bfloat16* __restrict__ A2, int ldA,
             const __nv_bfloat16* __restrict__ W2, int ldW,
             const float* __restrict__ bias,
             __half* __restrict__ C3, int N, int K)
{
    extern __shared__ __align__(256) char smraw[];
    const uint32_t base = smem_u32(smraw);
    const int tid = threadIdx.x;
    const int bm = blockIdx.y * 64, bn = blockIdx.x * 128;
    const int lane = tid & 31, warp = tid >> 5;
    const int wm = warp & 1, wn = warp >> 1;       // 2 x 2, warp tile 32x64
    const int nkc = K / BK;
    const int nch = 3 * nkc;

    float acc[2][8][4];
    #pragma unroll
    for (int i = 0; i < 2; i++)
        #pragma unroll
        for (int j = 0; j < 8; j++)
            #pragma unroll
            for (int k = 0; k < 4; k++) acc[i][j][k] = 0.f;

    auto issue_load = [&](int i, int st) {
        int s = i / nkc, kc = i - s * nkc;
        int ao = ((s == 2) ? K : 0) + kc * BK;
        int wo = ((s == 1) ? K : 0) + kc * BK;
        uint32_t smA = base + st * FSTGH;
        uint32_t smB = smA + ASTGH;
        const __nv_bfloat16* As = A2 + (size_t)bm * ldA + ao;
        const __nv_bfloat16* Ws = W2 + (size_t)bn * ldW + wo;
        #pragma unroll
        for (int j = 0; j < 2; j++) {
            int u = j * 128 + tid;
            int r = u >> 2, cc = (u & 3) * 8;
            cp16(smA + (uint32_t)(r * AST + cc) * 2, As + (size_t)r * ldA + cc);
        }
        #pragma unroll
        for (int j = 0; j < 4; j++) {
            int u = j * 128 + tid;
            int r = u >> 2, cc = (u & 3) * 8;
            cp16(smB + (uint32_t)(r * AST + cc) * 2, Ws + (size_t)r * ldW + cc);
        }
        asm volatile("cp.async.commit_group;\n" ::: "memory");
    };

    const int arow = wm * 32 + ((lane >> 3) & 1) * 8 + (lane & 7);
    const int akof = ((lane >> 4) & 1) * 8;
    const int brow = wn * 64 + ((lane >> 4) & 1) * 8 + (lane & 7);
    const int bkof = ((lane >> 3) & 1) * 8;

    issue_load(0, 0);
    if (nch > 1) issue_load(1, 1);

    for (int i = 0; i < nch; i++) {
        if (i == nch - 1) asm volatile("cp.async.wait_group 0;\n" ::: "memory");
        else              asm volatile("cp.async.wait_group 1;\n" ::: "memory");
        __syncthreads();
        if (i + 2 < nch) issue_load(i + 2, (i + 2) % NSTAGE_H);

        uint32_t smA = base + (i % NSTAGE_H) * FSTGH;
        uint32_t smB = smA + ASTGH;
        #pragma unroll
        for (int kk = 0; kk < 2; kk++) {
            const int k0 = kk * 16;
            uint32_t a[2][4];
            #pragma unroll
            for (int fm = 0; fm < 2; fm++)
                ldsm4(a[fm][0], a[fm][1], a[fm][2], a[fm][3],
                      smA + (uint32_t)((arow + fm * 16) * AST + k0 + akof) * 2);
            #pragma unroll
            for (int fb = 0; fb < 4; fb++) {
                uint32_t b0, b1, b2, b3;
                ldsm4(b0, b1, b2, b3,
                      smB + (uint32_t)((brow + fb * 16) * AST + k0 + bkof) * 2);
                #pragma unroll
                for (int fm = 0; fm < 2; fm++) {
                    mma16816(acc[fm][2 * fb],     a[fm], b0, b1);
                    mma16816(acc[fm][2 * fb + 1], a[fm], b2, b3);
                }
            }
        }
        __syncthreads();
    }

    const int lr = lane >> 2, lc = (lane & 3) * 2;
    #pragma unroll
    for (int fm = 0; fm < 2; fm++) {
        #pragma unroll
        for (int fn = 0; fn < 8; fn++) {
            float* cc = acc[fm][fn];
            int m0 = bm + wm * 32 + fm * 16 + lr;
            int n0 = bn + wn * 64 + fn * 8 + lc;
            float b0 = bias[n0], b1 = bias[n0 + 1];
            *(half2*)&C3[(size_t)m0 * N + n0]       = __floats2half2_rn(cc[0] + b0, cc[1] + b1);
            *(half2*)&C3[(size_t)(m0 + 8) * N + n0] = __floats2half2_rn(cc[2] + b0, cc[3] + b1);
        }
    }
}

// ================= fused flash attention (fp16, BQ=128, 256 threads) =================
#define BQ 128
#define BKC 64
#define QST 72
#define FTILEQ (128 * QST * 2)
#define FTILE (64 * QST * 2)
#define FSTG (2 * FTILE)
#define FA_SMEM (FTILEQ + 2 * FSTG + 64)

__global__ __launch_bounds__(256)
void fattn(const __half* __restrict__ Qp, int ldq,
           const __half* __restrict__ Kp, int ldk,
           const __half* __restrict__ Vh, int ldv,
           const __half* __restrict__ pm, __half* __restrict__ Oh, int Tk)
{
    extern __shared__ __align__(256) char smraw[];
    const uint32_t base = smem_u32(smraw);
    const int tid = threadIdx.x, lane = tid & 31, warp = tid >> 5;
    const int bh = (int)blockIdx.y, b = bh >> 3, h = bh & 7;
    const int q0 = (int)blockIdx.x * BQ;

    const __half* Qb = Qp + (size_t)(b * LQ + q0) * ldq + h * HD;
    const __half* Kb = Kp + (size_t)b * Tk * ldk + h * HD;
    const __half* Vb = Vh + (size_t)b * Tk * ldv + h * HD;

    // Q tile (128 rows)
    #pragma unroll
    for (int j = 0; j < 4; j++) {
        int u = j * 256 + tid, r = u >> 3, c8 = (u & 7) * 8;
        cp16(base + (uint32_t)(r * QST + c8) * 2, Qb + (size_t)r * ldq + c8);
    }
    asm volatile("cp.async.commit_group;\n" ::: "memory");

    // ones columns (64..71) in both stages' V tiles
    if (tid < 128) {
        int r = tid >> 1, cq = (tid & 1) * 4;
        #pragma unroll
        for (int st = 0; st < 2; st++) {
            size_t off = (size_t)FTILEQ + (size_t)st * FSTG + FTILE
                       + (size_t)(r * QST + 64 + cq) * 2;
            *(uint2*)(smraw + off) = make_uint2(0x3C003C00u, 0x3C003C00u);
        }
    }

    const int nc = Tk / BKC;
    auto load_chunk = [&](int ci, int st) {
        uint32_t sb = base + FTILEQ + st * FSTG;
        const __half* Kc = Kb + (size_t)ci * BKC * ldk;
        const __half* Vc = Vb + (size_t)ci * BKC * ldv;
        #pragma unroll
        for (int j = 0; j < 2; j++) {
            int u = j * 256 + tid, r = u >> 3, c8 = (u & 7) * 8;
            uint32_t off = (uint32_t)(r * QST + c8) * 2;
            cp16(sb + off,         Kc + (size_t)r * ldk + c8);
            cp16(sb + FTILE + off, Vc + (size_t)r * ldv + c8);
        }
        asm volatile("cp.async.commit_group;\n" ::: "memory");
    };

    load_chunk(0, 0);
    asm volatile("cp.async.wait_group 1;\n" ::: "memory");
    __syncthreads();

    const int qrow = warp * 16 + ((lane >> 3) & 1) * 8 + (lane & 7);
    const int qko  = ((lane >> 4) & 1) * 8;
    uint32_t qf[4][4];
    #pragma unroll
    for (int ds = 0; ds < 4; ds++)
        ldsm4(qf[ds][0], qf[ds][1], qf[ds][2], qf[ds][3],
              base + (uint32_t)(qrow * QST + ds * 16 + qko) * 2);

    load_chunk(1, 1);

    float o[8][4], osum[4];
    #pragma unroll
    for (int i = 0; i < 8; i++)
        #pragma unroll
        for (int j = 0; j < 4; j++) o[i][j] = 0.f;
    #pragma unroll
    for (int j = 0; j < 4; j++) osum[j] = 0.f;

    const float SC  = 0.125f * 1.44269504088896f;
    const float L2E = 1.44269504088896f;
    const int lr = lane >> 2, lc = (lane & 3) * 2;
    const int krow = ((lane >> 4) & 1) * 8 + (lane & 7);
    const int kko  = ((lane >> 3) & 1) * 8;
    const int vrow = lane & 15;
    const int vco  = ((lane >> 4) & 1) * 8;
    const int qr_g = q0 + warp * 16 + lr;

    for (int ci = 0; ci < nc; ci++) {
        if (ci == nc - 1) asm volatile("cp.async.wait_group 0;\n" ::: "memory");
        else              asm volatile("cp.async.wait_group 1;\n" ::: "memory");
        __syncthreads();

        uint32_t sb = base + FTILEQ + (ci & 1) * FSTG;

        // ---- S = Q·K^T ----
        float s[8][4];
        #pragma unroll
        for (int i = 0; i < 8; i++)
            #pragma unroll
            for (int j = 0; j < 4; j++) s[i][j] = 0.f;
        #pragma unroll
        for (int ds = 0; ds < 4; ds++) {
            #pragma unroll
            for (int g = 0; g < 4; g++) {
                uint32_t b0, b1, b2, b3;
                ldsm4(b0, b1, b2, b3,
                      sb + (uint32_t)((g * 16 + krow) * QST + ds * 16 + kko) * 2);
                mma16816h(s[2 * g],     qf[ds], b0, b1);
                mma16816h(s[2 * g + 1], qf[ds], b2, b3);
            }
        }

        // ---- probs as fp16 fragments ----
        uint32_t ph[4][4];
        #pragma unroll
        for (int nt = 0; nt < 8; nt++) {
            float t0 = s[nt][0] * SC, t1 = s[nt][1] * SC;
            float t2 = s[nt][2] * SC, t3 = s[nt][3] * SC;
            if (pm) {
                const __half* pmr = pm + (size_t)qr_g * Tk + ci * BKC + nt * 8 + lc;
                float2 m0 = __half22float2(*(const half2*)pmr);
                float2 m1 = __half22float2(*(const half2*)(pmr + (size_t)8 * Tk));
                t0 = fmaf(m0.x, L2E, t0); t1 = fmaf(m0.y, L2E, t1);
                t2 = fmaf(m1.x, L2E, t2); t3 = fmaf(m1.y, L2E, t3);
            }
            int j = nt >> 1, qi = (nt & 1) * 2;
            ph[j][qi]     = packex2h2(t0, t1);
            ph[j][qi + 1] = packex2h2(t2, t3);
        }

        // ---- O += P·V + row sums via ones columns ----
        uint32_t vb = sb + FTILE;
        #pragma unroll
        for (int ks = 0; ks < 4; ks++) {
            const uint32_t* pf = ph[ks];
            #pragma unroll
            for (int g = 0; g < 4; g++) {
                uint32_t b0, b1, b2, b3;
                ldsm4t(b0, b1, b2, b3,
                       vb + (uint32_t)((ks * 16 + vrow) * QST + g * 16 + vco) * 2);
                mma16816h(o[2 * g],     pf, b0, b1);
                mma16816h(o[2 * g + 1], pf, b2, b3);
            }
            {
                uint32_t b0, b1, b2, b3;
                ldsm4t(b0, b1, b2, b3,
                       vb + (uint32_t)((ks * 16 + vrow) * QST + 64 + vco) * 2);
                mma16816h(osum, pf, b0, b1);
            }
        }

        __syncthreads();
        if (ci + 2 < nc) load_chunk(ci + 2, ci & 1);
    }

    float inv0 = 1.0f / osum[0], inv1 = 1.0f / osum[2];

    const size_t row0 = (size_t)(b * LQ + qr_g);
    #pragma unroll
    for (int nt = 0; nt < 8; nt++) {
        int col = h * HD + nt * 8 + lc;
        *(half2*)&Oh[row0 * D + col] =
            __floats2half2_rn(o[nt][0] * inv0, o[nt][1] * inv0);
        *(half2*)&Oh[(row0 + 8) * D + col] =
            __floats2half2_rn(o[nt][2] * inv1, o[nt][3] * inv1);
    }
}

// ---------------- elementwise converts ----------------
__global__ void hconv(const float* __restrict__ src, __half* __restrict__ dst)
{
    size_t i = (size_t)blockIdx.x * 256 + threadIdx.x;
    dst[i] = __float2half(src[i]);
}

// split KV rows of xw_qkv -> g_wkv2 (per block: rows D..3D), bf16 hi|lo
__global__ void split_kv(const float* __restrict__ xw_qkv, __nv_bfloat16* __restrict__ dst)
{
    int c = blockIdx.x * 256 + threadIdx.x;
    int g = blockIdx.y;
    int i = g / (2 * D), r = g % (2 * D);
    float x = xw_qkv[((size_t)i * 3 * D + D + r) * D + c];
    __nv_bfloat16 h, l; split2(x, h, l);
    dst[(size_t)g * 2 * D + c] = h;
    dst[(size_t)g * 2 * D + D + c] = l;
}

// transpose+split: proj_w[D, D_IN] -> wT2[D_IN, 2*D]
__global__ void tsplit_proj(const float* __restrict__ pw, __nv_bfloat16* __restrict__ wT2)
{
    int k = blockIdx.x * 256 + threadIdx.x;
    int c = blockIdx.y;
    float x = pw[(size_t)k * D_IN + c];
    __nv_bfloat16 h, l; split2(x, h, l);
    wT2[(size_t)c * 2 * D + k] = h;
    wT2[(size_t)c * 2 * D + D + k] = l;
}

// folded KV bias for [Kall | Vall] layout
__global__ void kvbias_kernel(const float* __restrict__ xw_qkv, const float* __restrict__ xb_qkv,
                              const float* __restrict__ proj_b, float* __restrict__ bc)
{
    __shared__ float sh[32];
    int g = blockIdx.x;
    int wrow;
    if (g < 3072) { int i = g >> 9, n = g & 511; wrow = i * 3 * D + D + n; }
    else          { int gg = g - 3072; int i = gg >> 9, n = gg & 511; wrow = i * 3 * D + 2 * D + n; }
    const float* wr = xw_qkv + (size_t)wrow * D;
    float s = 0.f;
    for (int k = threadIdx.x; k < D; k += 256) s += wr[k] * proj_b[k];
    float tot = block_sum256(s, sh);
    if (threadIdx.x == 0) bc[g] = tot + xb_qkv[wrow];
}

// ---------------- LayerNorm -> fp16 ----------------
__global__ void ln_half(const float* __restrict__ x, const float* __restrict__ g,
                        const float* __restrict__ b, __half* __restrict__ y)
{
    __shared__ float sh[32];
    const int row = blockIdx.x, tid = threadIdx.x;
    const float* xr = x + (size_t)row * D;
    float2 v = *(const float2*)&xr[tid * 2];
    float total = block_sum256(v.x + v.y, sh);
    float mean = total * (1.0f / D);
    float d0 = v.x - mean, d1 = v.y - mean;
    float sq = block_sum256(d0 * d0 + d1 * d1, sh);
    float inv = rsqrtf(sq * (1.0f / D) + 1e-5f);
    float2 go = *(const float2*)&g[tid * 2];
    float2 bo = *(const float2*)&b[tid * 2];
    ((half2*)(y + (size_t)row * D))[tid] =
        __floats2half2_rn(d0 * inv * go.x + bo.x, d1 * inv * go.y + bo.y);
}

// ---------------- plain LayerNorm (final) ----------------
__global__ void ln_kernel(const float* __restrict__ x, const float* __restrict__ g,
                          const float* __restrict__ b, float* __restrict__ y)
{
    __shared__ float sh[32];
    const int row = blockIdx.x, tid = threadIdx.x;
    const float* xr = x + (size_t)row * D;
    float2 v = *(const float2*)&xr[tid * 2];
    float total = block_sum256(v.x + v.y, sh);
    float mean = total * (1.0f / D);
    float d0 = v.x - mean, d1 = v.y - mean;
    float sq = block_sum256(d0 * d0 + d1 * d1, sh);
    float inv = rsqrtf(sq * (1.0f / D) + 1e-5f);
    float2 go = *(const float2*)&g[tid * 2];
    float2 bo = *(const float2*)&b[tid * 2];
    float2 o;
    o.x = d0 * inv * go.x + bo.x;
    o.y = d1 * inv * go.y + bo.y;
    *(float2*)&y[(size_t)row * D + tid * 2] = o;
}

// ---------------- all 6 relative-time masks (fp16 out) ----------------
__global__ void mask6_kernel(const float* __restrict__ rel_bias, const float* __restrict__ ms,
                             __half* __restrict__ pm6)
{
    int k = blockIdx.x * 256 + threadIdx.x;
    int q = blockIdx.y;
    int z = blockIdx.z;
    float tau = (float)q * (4095.0f / 255.0f);
    float dt = (float)k - tau;
    float c = fminf(fmaxf(dt, -128.f), 128.f);
    int idx = (int)c + 128;
    float zz = dt * (1.0f / 32.0f);
    float lg = logf(expf(-0.5f * zz * zz) + 1e-6f);
    pm6[(size_t)z * LQ * T + (size_t)q * T + k] =
        __float2half(ms[z] * (rel_bias[z * 257 + idx] + lg));
}

// ---------------- misc ----------------
__global__ void bcast_latents(const float* __restrict__ src, float* __restrict__ dst)
{
    int i = blockIdx.x * 256 + threadIdx.x;
    dst[i] = src[i % (LQ * D)];
}

__global__ void mean_kernel(const float* __restrict__ x, float* __restrict__ out)
{
    int i = blockIdx.x * 256 + threadIdx.x;
    int b = i / D, d = i % D;
    float s = 0.f;
    for (int q = 0; q < LQ; q++) s += x[((size_t)b * LQ + q) * D + d];
    out[i] = s * (1.0f / LQ);
}

// ---------------- host orchestration ----------------
extern "C" void kernel_launch(void* const* d_in, const int* in_sizes, int n_in,
                              void* d_out, int out_size)
{
    (void)in_sizes; (void)n_in; (void)out_size;
    const float* tokens     = (const float*)d_in[0];
    const float* proj_w     = (const float*)d_in[1];
    const float* proj_b     = (const float*)d_in[2];
    const float* latents    = (const float*)d_in[3];
    const float* lnx_g      = (const float*)d_in[4];
    const float* lnx_b      = (const float*)d_in[5];
    const float* xw_qkv     = (const float*)d_in[6];
    const float* xb_qkv     = (const float*)d_in[7];
    const float* xw_o       = (const float*)d_in[8];
    const float* xb_o       = (const float*)d_in[9];
    const float* rel_bias   = (const float*)d_in[10];
    const float* mask_scale = (const float*)d_in[11];
    const float* mx_w1      = (const float*)d_in[12];
    const float* mx_b1      = (const float*)d_in[13];
    const float* mx_w2      = (const float*)d_in[14];
    const float* mx_b2      = (const float*)d_in[15];
    const float* lns_g      = (const float*)d_in[16];
    const float* lns_b      = (const float*)d_in[17];
    const float* sw_qkv     = (const float*)d_in[18];
    const float* sb_qkv     = (const float*)d_in[19];
    const float* sw_o       = (const float*)d_in[20];
    const float* sb_o       = (const float*)d_in[21];
    const float* ms_w1      = (const float*)d_in[22];
    const float* ms_b1      = (const float*)d_in[23];
    const float* ms_w2      = (const float*)d_in[24];
    const float* ms_b2      = (const float*)d_in[25];
    const float* lno_g      = (const float*)d_in[26];
    const float* lno_b      = (const float*)d_in[27];
    float* out = (float*)d_out;

    cudaFuncSetAttribute(gemm_b16<0>, cudaFuncAttributeMaxDynamicSharedMemorySize, GSM);
    cudaFuncSetAttribute(gemm_h16<0>, cudaFuncAttributeMaxDynamicSharedMemorySize, GSMH);
    cudaFuncSetAttribute(gemm_h16<1>, cudaFuncAttributeMaxDynamicSharedMemorySize, GSMH);
    cudaFuncSetAttribute(gemm_h16<2>, cudaFuncAttributeMaxDynamicSharedMemorySize, GSMH);
    cudaFuncSetAttribute(gemm_bf,     cudaFuncAttributeMaxDynamicSharedMemorySize, GSMF);
    cudaFuncSetAttribute(fattn,       cudaFuncAttributeMaxDynamicSharedMemorySize, FA_SMEM);

    float *plat, *ptmpf, *pbc, *pzb;
    __half *pmask6, *ptokh, *ptmph, *phidh, *path, *pqh, *pkallh, *pvallh, *psqh, *pwch,
           *pwxqkvh, *pwxoh, *pwmx1h, *pwmx2h, *pwsqkvh, *pwsoh, *pwms1h, *pwms2h;
    __nv_bfloat16 *pwkv2, *pwpT2;
    cudaGetSymbolAddress((void**)&plat,    g_lat);
    cudaGetSymbolAddress((void**)&ptmpf,   g_tmpf);
    cudaGetSymbolAddress((void**)&pmask6,  g_mask6);
    cudaGetSymbolAddress((void**)&pbc,     g_bc);
    cudaGetSymbolAddress((void**)&pzb,     g_zerob);
    cudaGetSymbolAddress((void**)&ptokh,   g_tokh);
    cudaGetSymbolAddress((void**)&ptmph,   g_tmph);
    cudaGetSymbolAddress((void**)&phidh,   g_hidh);
    cudaGetSymbolAddress((void**)&path,    g_ath);
    cudaGetSymbolAddress((void**)&pqh,     g_qh);
    cudaGetSymbolAddress((void**)&pkallh,  g_kallh);
    cudaGetSymbolAddress((void**)&pvallh,  g_vallh);
    cudaGetSymbolAddress((void**)&psqh,    g_sqh);
    cudaGetSymbolAddress((void**)&pwch,    g_wch);
    cudaGetSymbolAddress((void**)&pwxqkvh, g_wxqkvh);
    cudaGetSymbolAddress((void**)&pwxoh,   g_wxoh);
    cudaGetSymbolAddress((void**)&pwmx1h,  g_wmx1h);
    cudaGetSymbolAddress((void**)&pwmx2h,  g_wmx2h);
    cudaGetSymbolAddress((void**)&pwsqkvh, g_wsqkvh);
    cudaGetSymbolAddress((void**)&pwsoh,   g_wsoh);
    cudaGetSymbolAddress((void**)&pwms1h,  g_wms1h);
    cudaGetSymbolAddress((void**)&pwms2h,  g_wms2h);
    cudaGetSymbolAddress((void**)&pwkv2,   g_wkv2);
    cudaGetSymbolAddress((void**)&pwpT2,   g_wpT2);

    const int BT = B * T, BL = B * LQ;

    // ---- upfront: fp16 weight/token converts ----
    hconv<<<(NB * 3 * D * D) / 256, 256>>>(xw_qkv, pwxqkvh);
    hconv<<<(NB * D * D)     / 256, 256>>>(xw_o,   pwxoh);
    hconv<<<(NB * HID * D)   / 256, 256>>>(mx_w1,  pwmx1h);
    hconv<<<(NB * D * HID)   / 256, 256>>>(mx_w2,  pwmx2h);
    hconv<<<(NB * 3 * D * D) / 256, 256>>>(sw_qkv, pwsqkvh);
    hconv<<<(NB * D * D)     / 256, 256>>>(sw_o,   pwsoh);
    hconv<<<(NB * HID * D)   / 256, 256>>>(ms_w1,  pwms1h);
    hconv<<<(NB * D * HID)   / 256, 256>>>(ms_w2,  pwms2h);
    hconv<<<(BT * D_IN)      / 256, 256>>>(tokens, ptokh);

    // ---- fold (3-pass bf16 -> fp16): Wc = Wkv·Wp, layout [Kall | Vall] ----
    split_kv<<<dim3(D / 256, NB * 2 * D), 256>>>(xw_qkv, pwkv2);
    tsplit_proj<<<dim3(D / 256, D_IN), 256>>>(proj_w, pwpT2);
    for (int i = 0; i < NB; i++) {
        gemm_bf<<<dim3(D_IN / 128, 512 / 64), 128, GSMF>>>(
            pwkv2 + (size_t)(i * 2 * D) * 2 * D, 2 * D,
            pwpT2, 2 * D, pzb, pwch + (size_t)(i * 512) * D_IN, D_IN, D);
        gemm_bf<<<dim3(D_IN / 128, 512 / 64), 128, GSMF>>>(
            pwkv2 + (size_t)(i * 2 * D + 512) * 2 * D, 2 * D,
            pwpT2, 2 * D, pzb, pwch + (size_t)(3072 + i * 512) * D_IN, D_IN, D);
    }
    kvbias_kernel<<<KVN, 256>>>(xw_qkv, xb_qkv, proj_b, pbc);

    // ---- Kall / Vall for all 6 blocks (single-pass fp16, K=256) ----
    gemm_b16<0><<<dim3(3072 / 128, BT / 128), 256, GSM>>>(
        ptokh, D_IN, pwch, D_IN, pbc, nullptr, pkallh, 3072, D_IN);
    gemm_b16<0><<<dim3(3072 / 128, BT / 128), 256, GSM>>>(
        ptokh, D_IN, pwch + (size_t)3072 * D_IN, D_IN, pbc + 3072,
        nullptr, pvallh, 3072, D_IN);

    mask6_kernel<<<dim3(T / 256, LQ, NB), 256>>>(rel_bias, mask_scale, pmask6);
    bcast_latents<<<(BL * D) / 256, 256>>>(latents, plat);

    for (int i = 0; i < NB; i++) {
        // ---- cross attention ----
        ln_half<<<BL, 256>>>(plat, lnx_g + i * D, lnx_b + i * D, ptmph);
        gemm_h16<0><<<dim3(D / 128, BL / 64), 256, GSMH>>>(
            ptmph, D, pwxqkvh + (size_t)i * 3 * D * D, D,
            xb_qkv + (size_t)i * 3 * D, nullptr, pqh, D, D);
        fattn<<<dim3(LQ / BQ, B * H), 256, FA_SMEM>>>(
            pqh, D,
            pkallh + (size_t)i * 512, 3072,
            pvallh + (size_t)i * 512, 3072,
            pmask6 + (size_t)i * LQ * T, path, T);
        gemm_h16<2><<<dim3(D / 128, BL / 64), 256, GSMH>>>(
            path, D, pwxoh + (size_t)i * D * D, D, xb_o + i * D,
            plat, nullptr, D, D);

        // ---- cross MLP (pre-LN reuses lnx params) ----
        ln_half<<<BL, 256>>>(plat, lnx_g + i * D, lnx_b + i * D, ptmph);
        gemm_h16<1><<<dim3(HID / 128, BL / 64), 256, GSMH>>>(
            ptmph, D, pwmx1h + (size_t)i * HID * D, D, mx_b1 + i * HID,
            nullptr, phidh, HID, D);
        gemm_h16<2><<<dim3(D / 128, BL / 64), 256, GSMH>>>(
            phidh, HID, pwmx2h + (size_t)i * D * HID, HID, mx_b2 + i * D,
            plat, nullptr, D, HID);

        // ---- self attention ----
        ln_half<<<BL, 256>>>(plat, lns_g + i * D, lns_b + i * D, ptmph);
        gemm_h16<0><<<dim3((3 * D) / 128, BL / 64), 256, GSMH>>>(
            ptmph, D, pwsqkvh + (size_t)i * 3 * D * D, D,
            sb_qkv + (size_t)i * 3 * D, nullptr, psqh, 3 * D, D);
        fattn<<<dim3(LQ / BQ, B * H), 256, FA_SMEM>>>(
            psqh, 3 * D,
            psqh + D, 3 * D,
            psqh + 2 * D, 3 * D,
            nullptr, path, LQ);
        gemm_h16<2><<<dim3(D / 128, BL / 64), 256, GSMH>>>(
            path, D, pwsoh + (size_t)i * D * D, D, sb_o + i * D,
            plat, nullptr, D, D);

        // ---- self MLP ----
        ln_half<<<BL, 256>>>(plat, lns_g + i * D, lns_b + i * D, ptmph);
        gemm_h16<1><<<dim3(HID / 128, BL / 64), 256, GSMH>>>(
            ptmph, D, pwms1h + (size_t)i * HID * D, D, ms_b1 + i * HID,
            nullptr, phidh, HID, D);
        gemm_h16<2><<<dim3(D / 128, BL / 64), 256, GSMH>>>(
            phidh, HID, pwms2h + (size_t)i * D * HID, HID, ms_b2 + i * D,
            plat, nullptr, D, HID);
    }

    // final LN + mean over latents
    ln_kernel<<<BL, 256>>>(plat, lno_g, lno_b, ptmpf);
    mean_kernel<<<(B * D) / 256, 256>>>(ptmpf, out);
}

// round 16
// speedup vs baseline: 1.7168x; 1.1394x over previous
#include <cuda_runtime.h>
#include <cuda_bf16.h>
#include <cuda_fp16.h>
#include <cstdint>
#include <math.h>

// ---------------- problem constants ----------------
#define B   8
#define T   4096
#define D_IN 256
#define D   512
#define LQ  256
#define H   8
#define HD  64
#define NB  6
#define HID 2048
#define KVN (NB * 2 * D)

// ---------------- helpers ----------------
__device__ __forceinline__ uint32_t smem_u32(const void* p) {
    uint32_t a;
    asm("{ .reg .u64 t; cvta.to.shared.u64 t, %1; cvt.u32.u64 %0, t; }" : "=r"(a) : "l"(p));
    return a;
}
__device__ __forceinline__ void cp16(uint32_t dst, const void* src) {
    asm volatile("cp.async.cg.shared.global [%0], [%1], 16;\n" :: "r"(dst), "l"(src));
}
__device__ __forceinline__ void ldsm4(uint32_t& r0, uint32_t& r1, uint32_t& r2, uint32_t& r3,
                                      uint32_t addr) {
    asm volatile("ldmatrix.sync.aligned.m8n8.x4.shared.b16 {%0,%1,%2,%3}, [%4];"
        : "=r"(r0), "=r"(r1), "=r"(r2), "=r"(r3) : "r"(addr));
}
__device__ __forceinline__ void ldsm4t(uint32_t& r0, uint32_t& r1, uint32_t& r2, uint32_t& r3,
                                       uint32_t addr) {
    asm volatile("ldmatrix.sync.aligned.m8n8.x4.trans.shared.b16 {%0,%1,%2,%3}, [%4];"
        : "=r"(r0), "=r"(r1), "=r"(r2), "=r"(r3) : "r"(addr));
}
__device__ __forceinline__ void mma16816(float* c, const uint32_t* a, uint32_t b0, uint32_t b1) {
    asm volatile("mma.sync.aligned.m16n8k16.row.col.f32.bf16.bf16.f32 "
        "{%0,%1,%2,%3}, {%4,%5,%6,%7}, {%8,%9}, {%0,%1,%2,%3};"
        : "+f"(c[0]), "+f"(c[1]), "+f"(c[2]), "+f"(c[3])
        : "r"(a[0]), "r"(a[1]), "r"(a[2]), "r"(a[3]), "r"(b0), "r"(b1));
}
__device__ __forceinline__ void mma16816h(float* c, const uint32_t* a, uint32_t b0, uint32_t b1) {
    asm volatile("mma.sync.aligned.m16n8k16.row.col.f32.f16.f16.f32 "
        "{%0,%1,%2,%3}, {%4,%5,%6,%7}, {%8,%9}, {%0,%1,%2,%3};"
        : "+f"(c[0]), "+f"(c[1]), "+f"(c[2]), "+f"(c[3])
        : "r"(a[0]), "r"(a[1]), "r"(a[2]), "r"(a[3]), "r"(b0), "r"(b1));
}
__device__ __forceinline__ uint32_t packex2h2(float tlo, float thi) {
    uint32_t t, r;
    asm("cvt.rn.f16x2.f32 %0, %1, %2;" : "=r"(t) : "f"(thi), "f"(tlo));
    asm("ex2.approx.f16x2 %0, %1;" : "=r"(r) : "r"(t));
    return r;
}
__device__ __forceinline__ uint32_t hm2(uint32_t a, uint32_t b) {
    __half2 r = __hmul2(*(__half2*)&a, *(__half2*)&b);
    return *(uint32_t*)&r;
}
__device__ __forceinline__ void split2(float x, __nv_bfloat16& h, __nv_bfloat16& l) {
    h = __float2bfloat16(x);
    l = __float2bfloat16(x - __bfloat162float(h));
}

// ---------------- scratch ----------------
__device__ float g_lat [B*LQ*D];
__device__ float g_tmpf[B*LQ*D];
__device__ float g_bc  [KVN];
__device__ float g_zerob[D_IN];

__device__ __align__(256) __half g_w6   [NB*LQ*T];     // multiplicative mask weight exp2(m*log2e)
__device__ __align__(256) __half g_tokh [B*T*D_IN];
__device__ __align__(256) __half g_tmph [B*LQ*D];
__device__ __align__(256) __half g_hidh [B*LQ*HID];
__device__ __align__(256) __half g_ath  [B*LQ*D];
__device__ __align__(256) __half g_qh   [B*LQ*D];
__device__ __align__(256) __half g_kallh[(size_t)B*T*(NB*D)];
__device__ __align__(256) __half g_vallh[(size_t)B*T*(NB*D)];
__device__ __align__(256) __half g_sqh  [B*LQ*3*D];
// plain fp16 weights [N, K]
__device__ __align__(256) __half g_wch  [KVN*D_IN];
__device__ __align__(256) __half g_wxqkvh[NB*3*D*D];
__device__ __align__(256) __half g_wxoh  [NB*D*D];
__device__ __align__(256) __half g_wmx1h [NB*HID*D];
__device__ __align__(256) __half g_wmx2h [NB*D*HID];
__device__ __align__(256) __half g_wsqkvh[NB*3*D*D];
__device__ __align__(256) __half g_wsoh  [NB*D*D];
__device__ __align__(256) __half g_wms1h [NB*HID*D];
__device__ __align__(256) __half g_wms2h [NB*D*HID];
// bf16-split only for the weight-fold GEMM
__device__ __align__(256) __nv_bfloat16 g_wkv2[NB*2*D*2*D];
__device__ __align__(256) __nv_bfloat16 g_wpT2[D_IN*2*D];

// ---------------- reductions ----------------
__device__ __forceinline__ float block_sum256(float v, float* sh) {
    #pragma unroll
    for (int o = 16; o; o >>= 1) v += __shfl_xor_sync(0xffffffffu, v, o);
    if ((threadIdx.x & 31) == 0) sh[threadIdx.x >> 5] = v;
    __syncthreads();
    float t = (threadIdx.x < 8) ? sh[threadIdx.x] : 0.f;
    if (threadIdx.x < 32) {
        #pragma unroll
        for (int o = 4; o; o >>= 1) t += __shfl_xor_sync(0xffffffffu, t, o);
        if (threadIdx.x == 0) sh[0] = t;
    }
    __syncthreads();
    float r = sh[0];
    __syncthreads();
    return r;
}

// ================= fp16 single-pass GEMM: C = A·W^T + bias =================
#define BK 32
#define AST 40

// ---- 128x128 tile, 256 threads (KV production) ----
#define STG (128 * AST * 2)
#define NSTAGE 3
#define GSM (NSTAGE * 2 * STG)

template<int EPI>
__global__ __launch_bounds__(256)
void gemm_b16(const __half* __restrict__ A, int ldA,
              const __half* __restrict__ W, int ldW,
              const float* __restrict__ bias,
              float* __restrict__ C, __half* __restrict__ Ch, int N, int K)
{
    extern __shared__ __align__(256) char smraw[];
    const uint32_t base = smem_u32(smraw);
    const int tid = threadIdx.x;
    const int bm = blockIdx.y * 128, bn = blockIdx.x * 128;
    const int lane = tid & 31, warp = tid >> 5;
    const int wm = warp & 3, wn = warp >> 2;
    const int nch = K / BK;

    float acc[2][8][4];
    #pragma unroll
    for (int i = 0; i < 2; i++)
        #pragma unroll
        for (int j = 0; j < 8; j++)
            #pragma unroll
            for (int k = 0; k < 4; k++) acc[i][j][k] = 0.f;

    auto issue_load = [&](int kc, int st) {
        uint32_t smA = base + st * (2 * STG);
        uint32_t smB = smA + STG;
        const __half* As = A + (size_t)bm * ldA + kc * BK;
        const __half* Ws = W + (size_t)bn * ldW + kc * BK;
        #pragma unroll
        for (int j = 0; j < 2; j++) {
            int u = j * 256 + tid;
            int r = u >> 2, cc = (u & 3) * 8;
            cp16(smA + (uint32_t)(r * AST + cc) * 2, As + (size_t)r * ldA + cc);
            cp16(smB + (uint32_t)(r * AST + cc) * 2, Ws + (size_t)r * ldW + cc);
        }
        asm volatile("cp.async.commit_group;\n" ::: "memory");
    };

    const int arow = wm * 32 + ((lane >> 3) & 1) * 8 + (lane & 7);
    const int akof = ((lane >> 4) & 1) * 8;
    const int brow = wn * 64 + ((lane >> 4) & 1) * 8 + (lane & 7);
    const int bkof = ((lane >> 3) & 1) * 8;

    issue_load(0, 0);
    if (nch > 1) issue_load(1, 1);

    for (int i = 0; i < nch; i++) {
        if (i == nch - 1) asm volatile("cp.async.wait_group 0;\n" ::: "memory");
        else              asm volatile("cp.async.wait_group 1;\n" ::: "memory");
        __syncthreads();
        if (i + 2 < nch) issue_load(i + 2, (i + 2) % NSTAGE);

        uint32_t smA = base + (i % NSTAGE) * (2 * STG);
        uint32_t smB = smA + STG;
        #pragma unroll
        for (int kk = 0; kk < 2; kk++) {
            const int k0 = kk * 16;
            uint32_t a[2][4];
            #pragma unroll
            for (int fm = 0; fm < 2; fm++)
                ldsm4(a[fm][0], a[fm][1], a[fm][2], a[fm][3],
                      smA + (uint32_t)((arow + fm * 16) * AST + k0 + akof) * 2);
            #pragma unroll
            for (int fb = 0; fb < 4; fb++) {
                uint32_t b0, b1, b2, b3;
                ldsm4(b0, b1, b2, b3,
                      smB + (uint32_t)((brow + fb * 16) * AST + k0 + bkof) * 2);
                #pragma unroll
                for (int fm = 0; fm < 2; fm++) {
                    mma16816h(acc[fm][2 * fb],     a[fm], b0, b1);
                    mma16816h(acc[fm][2 * fb + 1], a[fm], b2, b3);
                }
            }
        }
        __syncthreads();
    }

    const int lr = lane >> 2, lc = (lane & 3) * 2;
    #pragma unroll
    for (int fm = 0; fm < 2; fm++) {
        #pragma unroll
        for (int fn = 0; fn < 8; fn++) {
            float* cc = acc[fm][fn];
            int m0 = bm + wm * 32 + fm * 16 + lr;
            int n0 = bn + wn * 64 + fn * 8 + lc;
            float b0 = bias[n0], b1 = bias[n0 + 1];
            float v00 = cc[0] + b0, v01 = cc[1] + b1;
            float v10 = cc[2] + b0, v11 = cc[3] + b1;
            if (EPI == 2) {
                float2 r0 = *(const float2*)&C[(size_t)m0 * N + n0];
                float2 r1 = *(const float2*)&C[(size_t)(m0 + 8) * N + n0];
                *(float2*)&C[(size_t)m0 * N + n0]       = make_float2(v00 + r0.x, v01 + r0.y);
                *(float2*)&C[(size_t)(m0 + 8) * N + n0] = make_float2(v10 + r1.x, v11 + r1.y);
            } else {
                *(half2*)&Ch[(size_t)m0 * N + n0]       = __floats2half2_rn(v00, v01);
                *(half2*)&Ch[(size_t)(m0 + 8) * N + n0] = __floats2half2_rn(v10, v11);
            }
        }
    }
}

// ---- 64x128 tile, 256 threads (8 warps, 2m x 4n, warp tile 32x32) ----
#define ASTGH (64 * AST * 2)
#define BSTGH (128 * AST * 2)
#define HSTG (ASTGH + BSTGH)
#define NSTAGE_H 3
#define GSMH (NSTAGE_H * HSTG)

template<int EPI>
__global__ __launch_bounds__(256)
void gemm_h16(const __half* __restrict__ A, int ldA,
              const __half* __restrict__ W, int ldW,
              const float* __restrict__ bias,
              float* __restrict__ C, __half* __restrict__ Ch, int N, int K)
{
    extern __shared__ __align__(256) char smraw[];
    const uint32_t base = smem_u32(smraw);
    const int tid = threadIdx.x;
    const int bm = blockIdx.y * 64, bn = blockIdx.x * 128;
    const int lane = tid & 31, warp = tid >> 5;
    const int wm = warp & 1, wn = warp >> 1;
    const int nch = K / BK;

    float acc[2][4][4];
    #pragma unroll
    for (int i = 0; i < 2; i++)
        #pragma unroll
        for (int j = 0; j < 4; j++)
            #pragma unroll
            for (int k = 0; k < 4; k++) acc[i][j][k] = 0.f;

    auto issue_load = [&](int kc, int st) {
        uint32_t smA = base + st * HSTG;
        uint32_t smB = smA + ASTGH;
        const __half* As = A + (size_t)bm * ldA + kc * BK;
        const __half* Ws = W + (size_t)bn * ldW + kc * BK;
        {
            int r = tid >> 2, cc = (tid & 3) * 8;
            cp16(smA + (uint32_t)(r * AST + cc) * 2, As + (size_t)r * ldA + cc);
        }
        #pragma unroll
        for (int j = 0; j < 2; j++) {
            int u = j * 256 + tid;
            int r = u >> 2, cc = (u & 3) * 8;
            cp16(smB + (uint32_t)(r * AST + cc) * 2, Ws + (size_t)r * ldW + cc);
        }
        asm volatile("cp.async.commit_group;\n" ::: "memory");
    };

    const int arow = wm * 32 + ((lane >> 3) & 1) * 8 + (lane & 7);
    const int akof = ((lane >> 4) & 1) * 8;
    const int brow = wn * 32 + ((lane >> 4) & 1) * 8 + (lane & 7);
    const int bkof = ((lane >> 3) & 1) * 8;

    issue_load(0, 0);
    if (nch > 1) issue_load(1, 1);

    for (int i = 0; i < nch; i++) {
        if (i == nch - 1) asm volatile("cp.async.wait_group 0;\n" ::: "memory");
        else              asm volatile("cp.async.wait_group 1;\n" ::: "memory");
        __syncthreads();
        if (i + 2 < nch) issue_load(i + 2, (i + 2) % NSTAGE_H);

        uint32_t smA = base + (i % NSTAGE_H) * HSTG;
        uint32_t smB = smA + ASTGH;
        #pragma unroll
        for (int kk = 0; kk < 2; kk++) {
            const int k0 = kk * 16;
            uint32_t a[2][4];
            #pragma unroll
            for (int fm = 0; fm < 2; fm++)
                ldsm4(a[fm][0], a[fm][1], a[fm][2], a[fm][3],
                      smA + (uint32_t)((arow + fm * 16) * AST + k0 + akof) * 2);
            #pragma unroll
            for (int g = 0; g < 2; g++) {
                uint32_t b0, b1, b2, b3;
                ldsm4(b0, b1, b2, b3,
                      smB + (uint32_t)((brow + g * 16) * AST + k0 + bkof) * 2);
                #pragma unroll
                for (int fm = 0; fm < 2; fm++) {
                    mma16816h(acc[fm][2 * g],     a[fm], b0, b1);
                    mma16816h(acc[fm][2 * g + 1], a[fm], b2, b3);
                }
            }
        }
        __syncthreads();
    }

    const int lr = lane >> 2, lc = (lane & 3) * 2;
    #pragma unroll
    for (int fm = 0; fm < 2; fm++) {
        #pragma unroll
        for (int fn = 0; fn < 4; fn++) {
            float* cc = acc[fm][fn];
            int m0 = bm + wm * 32 + fm * 16 + lr;
            int n0 = bn + wn * 32 + fn * 8 + lc;
            float b0 = bias[n0], b1 = bias[n0 + 1];
            float v00 = cc[0] + b0, v01 = cc[1] + b1;
            float v10 = cc[2] + b0, v11 = cc[3] + b1;
            if (EPI == 1) {
                v00 = 0.5f * v00 * (1.0f + erff(v00 * 0.70710678118654752f));
                v01 = 0.5f * v01 * (1.0f + erff(v01 * 0.70710678118654752f));
                v10 = 0.5f * v10 * (1.0f + erff(v10 * 0.70710678118654752f));
                v11 = 0.5f * v11 * (1.0f + erff(v11 * 0.70710678118654752f));
            }
            if (EPI == 2) {
                float2 r0 = *(const float2*)&C[(size_t)m0 * N + n0];
                float2 r1 = *(const float2*)&C[(size_t)(m0 + 8) * N + n0];
                *(float2*)&C[(size_t)m0 * N + n0]       = make_float2(v00 + r0.x, v01 + r0.y);
                *(float2*)&C[(size_t)(m0 + 8) * N + n0] = make_float2(v10 + r1.x, v11 + r1.y);
            } else {
                *(half2*)&Ch[(size_t)m0 * N + n0]       = __floats2half2_rn(v00, v01);
                *(half2*)&Ch[(size_t)(m0 + 8) * N + n0] = __floats2half2_rn(v10, v11);
            }
        }
    }
}

// ---- bf16-split 3-pass GEMM (64x128, 128 threads), plain fp16 out — weight fold ----
#define FSTGH (ASTGH + BSTGH)
#define GSMF (NSTAGE_H * FSTGH)

__global__ __launch_bounds__(128)
void gemm_bf(const __nv_bfloat16* __restrict__ A2, int ldA,
             const __nv_bfloat16* __restrict__ W2, int ldW,
             const float* __restrict__ bias,
             __half* __restrict__ C3, int N, int K)
{
    extern __shared__ __align__(256) char smraw[];
    const uint32_t base = smem_u32(smraw);
    const int tid = threadIdx.x;
    const int bm = blockIdx.y * 64, bn = blockIdx.x * 128;
    const int lane = tid & 31, warp = tid >> 5;
    const int wm = warp & 1, wn = warp >> 1;
    const int nkc = K / BK;
    const int nch = 3 * nkc;

    float acc[2][8][4];
    #pragma unroll
    for (int i = 0; i < 2; i++)
        #pragma unroll
        for (int j = 0; j < 8; j++)
            #pragma unroll
            for (int k = 0; k < 4; k++) acc[i][j][k] = 0.f;

    auto issue_load = [&](int i, int st) {
        int s = i / nkc, kc = i - s * nkc;
        int ao = ((s == 2) ? K : 0) + kc * BK;
        int wo = ((s == 1) ? K : 0) + kc * BK;
        uint32_t smA = base + st * FSTGH;
        uint32_t smB = smA + ASTGH;
        const __nv_bfloat16* As = A2 + (size_t)bm * ldA + ao;
        const __nv_bfloat16* Ws = W2 + (size_t)bn * ldW + wo;
        #pragma unroll
        for (int j = 0; j < 2; j++) {
            int u = j * 128 + tid;
            int r = u >> 2, cc = (u & 3) * 8;
            cp16(smA + (uint32_t)(r * AST + cc) * 2, As + (size_t)r * ldA + cc);
        }
        #pragma unroll
        for (int j = 0; j < 4; j++) {
            int u = j * 128 + tid;
            int r = u >> 2, cc = (u & 3) * 8;
            cp16(smB + (uint32_t)(r * AST + cc) * 2, Ws + (size_t)r * ldW + cc);
        }
        asm volatile("cp.async.commit_group;\n" ::: "memory");
    };

    const int arow = wm * 32 + ((lane >> 3) & 1) * 8 + (lane & 7);
    const int akof = ((lane >> 4) & 1) * 8;
    const int brow = wn * 64 + ((lane >> 4) & 1) * 8 + (lane & 7);
    const int bkof = ((lane >> 3) & 1) * 8;

    issue_load(0, 0);
    if (nch > 1) issue_load(1, 1);

    for (int i = 0; i < nch; i++) {
        if (i == nch - 1) asm volatile("cp.async.wait_group 0;\n" ::: "memory");
        else              asm volatile("cp.async.wait_group 1;\n" ::: "memory");
        __syncthreads();
        if (i + 2 < nch) issue_load(i + 2, (i + 2) % NSTAGE_H);

        uint32_t smA = base + (i % NSTAGE_H) * FSTGH;
        uint32_t smB = smA + ASTGH;
        #pragma unroll
        for (int kk = 0; kk < 2; kk++) {
            const int k0 = kk * 16;
            uint32_t a[2][4];
            #pragma unroll
            for (int fm = 0; fm < 2; fm++)
                ldsm4(a[fm][0], a[fm][1], a[fm][2], a[fm][3],
                      smA + (uint32_t)((arow + fm * 16) * AST + k0 + akof) * 2);
            #pragma unroll
            for (int fb = 0; fb < 4; fb++) {
                uint32_t b0, b1, b2, b3;
                ldsm4(b0, b1, b2, b3,
                      smB + (uint32_t)((brow + fb * 16) * AST + k0 + bkof) * 2);
                #pragma unroll
                for (int fm = 0; fm < 2; fm++) {
                    mma16816(acc[fm][2 * fb],     a[fm], b0, b1);
                    mma16816(acc[fm][2 * fb + 1], a[fm], b2, b3);
                }
            }
        }
        __syncthreads();
    }

    const int lr = lane >> 2, lc = (lane & 3) * 2;
    #pragma unroll
    for (int fm = 0; fm < 2; fm++) {
        #pragma unroll
        for (int fn = 0; fn < 8; fn++) {
            float* cc = acc[fm][fn];
            int m0 = bm + wm * 32 + fm * 16 + lr;
            int n0 = bn + wn * 64 + fn * 8 + lc;
            float b0 = bias[n0], b1 = bias[n0 + 1];
            *(half2*)&C3[(size_t)m0 * N + n0]       = __floats2half2_rn(cc[0] + b0, cc[1] + b1);
            *(half2*)&C3[(size_t)(m0 + 8) * N + n0] = __floats2half2_rn(cc[2] + b0, cc[3] + b1);
        }
    }
}

// ================= fused flash attention (fp16, BQ=128, 256 threads) =================
// Multiplicative mask weight w staged in smem; far warp-chunks use ph = w directly
// (no QK mma, no exp). Near chunks: p = w * ex2(SC*s) — exact identity.
#define BQ 128
#define BKC 64
#define QST 72
#define FTILEQ (128 * QST * 2)          // 18432
#define FTILE (64 * QST * 2)            // 9216
#define WTILE (128 * QST * 2)           // 18432
#define FSTG (2 * FTILE + WTILE)        // 36864
#define FA_SMEM (FTILEQ + 2 * FSTG + 64)

__global__ __launch_bounds__(256)
void fattn(const __half* __restrict__ Qp, int ldq,
           const __half* __restrict__ Kp, int ldk,
           const __half* __restrict__ Vh, int ldv,
           const __half* __restrict__ w6, __half* __restrict__ Oh, int Tk)
{
    extern __shared__ __align__(256) char smraw[];
    const uint32_t base = smem_u32(smraw);
    const int tid = threadIdx.x, lane = tid & 31, warp = tid >> 5;
    const int bh = (int)blockIdx.y, b = bh >> 3, h = bh & 7;
    const int q0 = (int)blockIdx.x * BQ;

    const __half* Qb = Qp + (size_t)(b * LQ + q0) * ldq + h * HD;
    const __half* Kb = Kp + (size_t)b * Tk * ldk + h * HD;
    const __half* Vb = Vh + (size_t)b * Tk * ldv + h * HD;

    // Q tile (128 rows)
    #pragma unroll
    for (int j = 0; j < 4; j++) {
        int u = j * 256 + tid, r = u >> 3, c8 = (u & 7) * 8;
        cp16(base + (uint32_t)(r * QST + c8) * 2, Qb + (size_t)r * ldq + c8);
    }
    asm volatile("cp.async.commit_group;\n" ::: "memory");

    // ones columns (64..71) in both stages' V tiles
    if (tid < 128) {
        int r = tid >> 1, cq = (tid & 1) * 4;
        #pragma unroll
        for (int st = 0; st < 2; st++) {
            size_t off = (size_t)FTILEQ + (size_t)st * FSTG + FTILE
                       + (size_t)(r * QST + 64 + cq) * 2;
            *(uint2*)(smraw + off) = make_uint2(0x3C003C00u, 0x3C003C00u);
        }
    }

    const int nc = Tk / BKC;
    auto load_chunk = [&](int ci, int st) {
        uint32_t sb = base + FTILEQ + st * FSTG;
        const __half* Kc = Kb + (size_t)ci * BKC * ldk;
        const __half* Vc = Vb + (size_t)ci * BKC * ldv;
        #pragma unroll
        for (int j = 0; j < 2; j++) {
            int u = j * 256 + tid, r = u >> 3, c8 = (u & 7) * 8;
            uint32_t off = (uint32_t)(r * QST + c8) * 2;
            cp16(sb + off,         Kc + (size_t)r * ldk + c8);
            cp16(sb + FTILE + off, Vc + (size_t)r * ldv + c8);
        }
        if (w6) {
            const __half* Wc = w6 + (size_t)q0 * Tk + ci * BKC;
            #pragma unroll
            for (int j = 0; j < 4; j++) {
                int u = j * 256 + tid, r = u >> 3, c8 = (u & 7) * 8;
                cp16(sb + 2 * FTILE + (uint32_t)(r * QST + c8) * 2,
                     Wc + (size_t)r * Tk + c8);
            }
        }
        asm volatile("cp.async.commit_group;\n" ::: "memory");
    };

    load_chunk(0, 0);
    asm volatile("cp.async.wait_group 1;\n" ::: "memory");
    __syncthreads();

    const int qrow = warp * 16 + ((lane >> 3) & 1) * 8 + (lane & 7);
    const int qko  = ((lane >> 4) & 1) * 8;
    uint32_t qf[4][4];
    #pragma unroll
    for (int ds = 0; ds < 4; ds++)
        ldsm4(qf[ds][0], qf[ds][1], qf[ds][2], qf[ds][3],
              base + (uint32_t)(qrow * QST + ds * 16 + qko) * 2);

    load_chunk(1, 1);

    float o[8][4], osum[4];
    #pragma unroll
    for (int i = 0; i < 8; i++)
        #pragma unroll
        for (int j = 0; j < 4; j++) o[i][j] = 0.f;
    #pragma unroll
    for (int j = 0; j < 4; j++) osum[j] = 0.f;

    const float SC  = 0.125f * 1.44269504088896f;
    const float TSTEP = 4095.0f / 255.0f;
    const float THR = 176.0f;
    const int lr = lane >> 2, lc = (lane & 3) * 2;
    const int krow = ((lane >> 4) & 1) * 8 + (lane & 7);
    const int kko  = ((lane >> 3) & 1) * 8;
    const int vrow = lane & 15;
    const int vco  = ((lane >> 4) & 1) * 8;
    const int qr_g = q0 + warp * 16 + lr;
    // warp-uniform attention window bounds (cross attention only)
    const float tau_lo = (float)(q0 + warp * 16) * TSTEP;
    const float tau_hi = tau_lo + 15.0f * TSTEP;
    const int wrow_l = ((lane >> 3) & 1) * 8 + (lane & 7);
    const int wko = ((lane >> 4) & 1) * 8;

    for (int ci = 0; ci < nc; ci++) {
        if (ci == nc - 1) asm volatile("cp.async.wait_group 0;\n" ::: "memory");
        else              asm volatile("cp.async.wait_group 1;\n" ::: "memory");
        __syncthreads();

        uint32_t sb = base + FTILEQ + (ci & 1) * FSTG;
        uint32_t wsm = sb + 2 * FTILE;

        uint32_t ph[4][4];
        bool near = true;
        if (w6) {
            // load w fragments in A layout
            #pragma unroll
            for (int ks = 0; ks < 4; ks++)
                ldsm4(ph[ks][0], ph[ks][1], ph[ks][2], ph[ks][3],
                      wsm + (uint32_t)((warp * 16 + wrow_l) * QST + ks * 16 + wko) * 2);
            float k0f = (float)(ci * BKC);
            near = !((k0f + 63.0f < tau_lo - THR) || (k0f > tau_hi + THR));
        }

        if (near) {
            // ---- S = Q·K^T ----
            float s[8][4];
            #pragma unroll
            for (int i = 0; i < 8; i++)
                #pragma unroll
                for (int j = 0; j < 4; j++) s[i][j] = 0.f;
            #pragma unroll
            for (int ds = 0; ds < 4; ds++) {
                #pragma unroll
                for (int g = 0; g < 4; g++) {
                    uint32_t b0, b1, b2, b3;
                    ldsm4(b0, b1, b2, b3,
                          sb + (uint32_t)((g * 16 + krow) * QST + ds * 16 + kko) * 2);
                    mma16816h(s[2 * g],     qf[ds], b0, b1);
                    mma16816h(s[2 * g + 1], qf[ds], b2, b3);
                }
            }
            // ---- probs ----
            #pragma unroll
            for (int nt = 0; nt < 8; nt++) {
                float t0 = s[nt][0] * SC, t1 = s[nt][1] * SC;
                float t2 = s[nt][2] * SC, t3 = s[nt][3] * SC;
                uint32_t e01 = packex2h2(t0, t1);
                uint32_t e23 = packex2h2(t2, t3);
                int j = nt >> 1, qi = (nt & 1) * 2;
                if (w6) {
                    ph[j][qi]     = hm2(ph[j][qi], e01);
                    ph[j][qi + 1] = hm2(ph[j][qi + 1], e23);
                } else {
                    ph[j][qi]     = e01;
                    ph[j][qi + 1] = e23;
                }
            }
        }
        // far: ph stays = w fragments (p = w exactly)

        // ---- O += P·V + row sums via ones columns ----
        uint32_t vb = sb + FTILE;
        #pragma unroll
        for (int ks = 0; ks < 4; ks++) {
            const uint32_t* pf = ph[ks];
            #pragma unroll
            for (int g = 0; g < 4; g++) {
                uint32_t b0, b1, b2, b3;
                ldsm4t(b0, b1, b2, b3,
                       vb + (uint32_t)((ks * 16 + vrow) * QST + g * 16 + vco) * 2);
                mma16816h(o[2 * g],     pf, b0, b1);
                mma16816h(o[2 * g + 1], pf, b2, b3);
            }
            {
                uint32_t b0, b1, b2, b3;
                ldsm4t(b0, b1, b2, b3,
                       vb + (uint32_t)((ks * 16 + vrow) * QST + 64 + vco) * 2);
                mma16816h(osum, pf, b0, b1);
            }
        }

        __syncthreads();
        if (ci + 2 < nc) load_chunk(ci + 2, ci & 1);
    }

    float inv0 = 1.0f / osum[0], inv1 = 1.0f / osum[2];

    const size_t row0 = (size_t)(b * LQ + qr_g);
    #pragma unroll
    for (int nt = 0; nt < 8; nt++) {
        int col = h * HD + nt * 8 + lc;
        *(half2*)&Oh[row0 * D + col] =
            __floats2half2_rn(o[nt][0] * inv0, o[nt][1] * inv0);
        *(half2*)&Oh[(row0 + 8) * D + col] =
            __floats2half2_rn(o[nt][2] * inv1, o[nt][3] * inv1);
    }
}

// ---------------- elementwise converts ----------------
__global__ void hconv(const float* __restrict__ src, __half* __restrict__ dst)
{
    size_t i = (size_t)blockIdx.x * 256 + threadIdx.x;
    dst[i] = __float2half(src[i]);
}

// split KV rows of xw_qkv -> g_wkv2 (per block: rows D..3D), bf16 hi|lo
__global__ void split_kv(const float* __restrict__ xw_qkv, __nv_bfloat16* __restrict__ dst)
{
    int c = blockIdx.x * 256 + threadIdx.x;
    int g = blockIdx.y;
    int i = g / (2 * D), r = g % (2 * D);
    float x = xw_qkv[((size_t)i * 3 * D + D + r) * D + c];
    __nv_bfloat16 h, l; split2(x, h, l);
    dst[(size_t)g * 2 * D + c] = h;
    dst[(size_t)g * 2 * D + D + c] = l;
}

// transpose+split: proj_w[D, D_IN] -> wT2[D_IN, 2*D]
__global__ void tsplit_proj(const float* __restrict__ pw, __nv_bfloat16* __restrict__ wT2)
{
    int k = blockIdx.x * 256 + threadIdx.x;
    int c = blockIdx.y;
    float x = pw[(size_t)k * D_IN + c];
    __nv_bfloat16 h, l; split2(x, h, l);
    wT2[(size_t)c * 2 * D + k] = h;
    wT2[(size_t)c * 2 * D + D + k] = l;
}

// folded KV bias for [Kall | Vall] layout
__global__ void kvbias_kernel(const float* __restrict__ xw_qkv, const float* __restrict__ xb_qkv,
                              const float* __restrict__ proj_b, float* __restrict__ bc)
{
    __shared__ float sh[32];
    int g = blockIdx.x;
    int wrow;
    if (g < 3072) { int i = g >> 9, n = g & 511; wrow = i * 3 * D + D + n; }
    else          { int gg = g - 3072; int i = gg >> 9, n = gg & 511; wrow = i * 3 * D + 2 * D + n; }
    const float* wr = xw_qkv + (size_t)wrow * D;
    float s = 0.f;
    for (int k = threadIdx.x; k < D; k += 256) s += wr[k] * proj_b[k];
    float tot = block_sum256(s, sh);
    if (threadIdx.x == 0) bc[g] = tot + xb_qkv[wrow];
}

// ---------------- LayerNorm -> fp16 ----------------
__global__ void ln_half(const float* __restrict__ x, const float* __restrict__ g,
                        const float* __restrict__ b, __half* __restrict__ y)
{
    __shared__ float sh[32];
    const int row = blockIdx.x, tid = threadIdx.x;
    const float* xr = x + (size_t)row * D;
    float2 v = *(const float2*)&xr[tid * 2];
    float total = block_sum256(v.x + v.y, sh);
    float mean = total * (1.0f / D);
    float d0 = v.x - mean, d1 = v.y - mean;
    float sq = block_sum256(d0 * d0 + d1 * d1, sh);
    float inv = rsqrtf(sq * (1.0f / D) + 1e-5f);
    float2 go = *(const float2*)&g[tid * 2];
    float2 bo = *(const float2*)&b[tid * 2];
    ((half2*)(y + (size_t)row * D))[tid] =
        __floats2half2_rn(d0 * inv * go.x + bo.x, d1 * inv * go.y + bo.y);
}

// ---------------- plain LayerNorm (final) ----------------
__global__ void ln_kernel(const float* __restrict__ x, const float* __restrict__ g,
                          const float* __restrict__ b, float* __restrict__ y)
{
    __shared__ float sh[32];
    const int row = blockIdx.x, tid = threadIdx.x;
    const float* xr = x + (size_t)row * D;
    float2 v = *(const float2*)&xr[tid * 2];
    float total = block_sum256(v.x + v.y, sh);
    float mean = total * (1.0f / D);
    float d0 = v.x - mean, d1 = v.y - mean;
    float sq = block_sum256(d0 * d0 + d1 * d1, sh);
    float inv = rsqrtf(sq * (1.0f / D) + 1e-5f);
    float2 go = *(const float2*)&g[tid * 2];
    float2 bo = *(const float2*)&b[tid * 2];
    float2 o;
    o.x = d0 * inv * go.x + bo.x;
    o.y = d1 * inv * go.y + bo.y;
    *(float2*)&y[(size_t)row * D + tid * 2] = o;
}

// ---- all 6 masks as multiplicative fp16 weights: w = exp2(mask * log2e) ----
__global__ void mask6_kernel(const float* __restrict__ rel_bias, const float* __restrict__ ms,
                             __half* __restrict__ w6)
{
    int k = blockIdx.x * 256 + threadIdx.x;
    int q = blockIdx.y;
    int z = blockIdx.z;
    float tau = (float)q * (4095.0f / 255.0f);
    float dt = (float)k - tau;
    float c = fminf(fmaxf(dt, -128.f), 128.f);
    int idx = (int)c + 128;
    float zz = dt * (1.0f / 32.0f);
    float lg = logf(expf(-0.5f * zz * zz) + 1e-6f);
    float m = ms[z] * (rel_bias[z * 257 + idx] + lg);
    w6[(size_t)z * LQ * T + (size_t)q * T + k] =
        __float2half(exp2f(1.44269504088896f * m));
}

// ---------------- misc ----------------
__global__ void bcast_latents(const float* __restrict__ src, float* __restrict__ dst)
{
    int i = blockIdx.x * 256 + threadIdx.x;
    dst[i] = src[i % (LQ * D)];
}

__global__ void mean_kernel(const float* __restrict__ x, float* __restrict__ out)
{
    int i = blockIdx.x * 256 + threadIdx.x;
    int b = i / D, d = i % D;
    float s = 0.f;
    for (int q = 0; q < LQ; q++) s += x[((size_t)b * LQ + q) * D + d];
    out[i] = s * (1.0f / LQ);
}

// ---------------- host orchestration ----------------
extern "C" void kernel_launch(void* const* d_in, const int* in_sizes, int n_in,
                              void* d_out, int out_size)
{
    (void)in_sizes; (void)n_in; (void)out_size;
    const float* tokens     = (const float*)d_in[0];
    const float* proj_w     = (const float*)d_in[1];
    const float* proj_b     = (const float*)d_in[2];
    const float* latents    = (const float*)d_in[3];
    const float* lnx_g      = (const float*)d_in[4];
    const float* lnx_b      = (const float*)d_in[5];
    const float* xw_qkv     = (const float*)d_in[6];
    const float* xb_qkv     = (const float*)d_in[7];
    const float* xw_o       = (const float*)d_in[8];
    const float* xb_o       = (const float*)d_in[9];
    const float* rel_bias   = (const float*)d_in[10];
    const float* mask_scale = (const float*)d_in[11];
    const float* mx_w1      = (const float*)d_in[12];
    const float* mx_b1      = (const float*)d_in[13];
    const float* mx_w2      = (const float*)d_in[14];
    const float* mx_b2      = (const float*)d_in[15];
    const float* lns_g      = (const float*)d_in[16];
    const float* lns_b      = (const float*)d_in[17];
    const float* sw_qkv     = (const float*)d_in[18];
    const float* sb_qkv     = (const float*)d_in[19];
    const float* sw_o       = (const float*)d_in[20];
    const float* sb_o       = (const float*)d_in[21];
    const float* ms_w1      = (const float*)d_in[22];
    const float* ms_b1      = (const float*)d_in[23];
    const float* ms_w2      = (const float*)d_in[24];
    const float* ms_b2      = (const float*)d_in[25];
    const float* lno_g      = (const float*)d_in[26];
    const float* lno_b      = (const float*)d_in[27];
    float* out = (float*)d_out;

    cudaFuncSetAttribute(gemm_b16<0>, cudaFuncAttributeMaxDynamicSharedMemorySize, GSM);
    cudaFuncSetAttribute(gemm_h16<0>, cudaFuncAttributeMaxDynamicSharedMemorySize, GSMH);
    cudaFuncSetAttribute(gemm_h16<1>, cudaFuncAttributeMaxDynamicSharedMemorySize, GSMH);
    cudaFuncSetAttribute(gemm_h16<2>, cudaFuncAttributeMaxDynamicSharedMemorySize, GSMH);
    cudaFuncSetAttribute(gemm_bf,     cudaFuncAttributeMaxDynamicSharedMemorySize, GSMF);
    cudaFuncSetAttribute(fattn,       cudaFuncAttributeMaxDynamicSharedMemorySize, FA_SMEM);

    float *plat, *ptmpf, *pbc, *pzb;
    __half *pw6, *ptokh, *ptmph, *phidh, *path, *pqh, *pkallh, *pvallh, *psqh, *pwch,
           *pwxqkvh, *pwxoh, *pwmx1h, *pwmx2h, *pwsqkvh, *pwsoh, *pwms1h, *pwms2h;
    __nv_bfloat16 *pwkv2, *pwpT2;
    cudaGetSymbolAddress((void**)&plat,    g_lat);
    cudaGetSymbolAddress((void**)&ptmpf,   g_tmpf);
    cudaGetSymbolAddress((void**)&pw6,     g_w6);
    cudaGetSymbolAddress((void**)&pbc,     g_bc);
    cudaGetSymbolAddress((void**)&pzb,     g_zerob);
    cudaGetSymbolAddress((void**)&ptokh,   g_tokh);
    cudaGetSymbolAddress((void**)&ptmph,   g_tmph);
    cudaGetSymbolAddress((void**)&phidh,   g_hidh);
    cudaGetSymbolAddress((void**)&path,    g_ath);
    cudaGetSymbolAddress((void**)&pqh,     g_qh);
    cudaGetSymbolAddress((void**)&pkallh,  g_kallh);
    cudaGetSymbolAddress((void**)&pvallh,  g_vallh);
    cudaGetSymbolAddress((void**)&psqh,    g_sqh);
    cudaGetSymbolAddress((void**)&pwch,    g_wch);
    cudaGetSymbolAddress((void**)&pwxqkvh, g_wxqkvh);
    cudaGetSymbolAddress((void**)&pwxoh,   g_wxoh);
    cudaGetSymbolAddress((void**)&pwmx1h,  g_wmx1h);
    cudaGetSymbolAddress((void**)&pwmx2h,  g_wmx2h);
    cudaGetSymbolAddress((void**)&pwsqkvh, g_wsqkvh);
    cudaGetSymbolAddress((void**)&pwsoh,   g_wsoh);
    cudaGetSymbolAddress((void**)&pwms1h,  g_wms1h);
    cudaGetSymbolAddress((void**)&pwms2h,  g_wms2h);
    cudaGetSymbolAddress((void**)&pwkv2,   g_wkv2);
    cudaGetSymbolAddress((void**)&pwpT2,   g_wpT2);

    const int BT = B * T, BL = B * LQ;

    // ---- upfront: fp16 weight/token converts ----
    hconv<<<(NB * 3 * D * D) / 256, 256>>>(xw_qkv, pwxqkvh);
    hconv<<<(NB * D * D)     / 256, 256>>>(xw_o,   pwxoh);
    hconv<<<(NB * HID * D)   / 256, 256>>>(mx_w1,  pwmx1h);
    hconv<<<(NB * D * HID)   / 256, 256>>>(mx_w2,  pwmx2h);
    hconv<<<(NB * 3 * D * D) / 256, 256>>>(sw_qkv, pwsqkvh);
    hconv<<<(NB * D * D)     / 256, 256>>>(sw_o,   pwsoh);
    hconv<<<(NB * HID * D)   / 256, 256>>>(ms_w1,  pwms1h);
    hconv<<<(NB * D * HID)   / 256, 256>>>(ms_w2,  pwms2h);
    hconv<<<(BT * D_IN)      / 256, 256>>>(tokens, ptokh);

    // ---- fold (3-pass bf16 -> fp16): Wc = Wkv·Wp, layout [Kall | Vall] ----
    split_kv<<<dim3(D / 256, NB * 2 * D), 256>>>(xw_qkv, pwkv2);
    tsplit_proj<<<dim3(D / 256, D_IN), 256>>>(proj_w, pwpT2);
    for (int i = 0; i < NB; i++) {
        gemm_bf<<<dim3(D_IN / 128, 512 / 64), 128, GSMF>>>(
            pwkv2 + (size_t)(i * 2 * D) * 2 * D, 2 * D,
            pwpT2, 2 * D, pzb, pwch + (size_t)(i * 512) * D_IN, D_IN, D);
        gemm_bf<<<dim3(D_IN / 128, 512 / 64), 128, GSMF>>>(
            pwkv2 + (size_t)(i * 2 * D + 512) * 2 * D, 2 * D,
            pwpT2, 2 * D, pzb, pwch + (size_t)(3072 + i * 512) * D_IN, D_IN, D);
    }
    kvbias_kernel<<<KVN, 256>>>(xw_qkv, xb_qkv, proj_b, pbc);

    // ---- Kall / Vall for all 6 blocks (single-pass fp16, K=256) ----
    gemm_b16<0><<<dim3(3072 / 128, BT / 128), 256, GSM>>>(
        ptokh, D_IN, pwch, D_IN, pbc, nullptr, pkallh, 3072, D_IN);
    gemm_b16<0><<<dim3(3072 / 128, BT / 128), 256, GSM>>>(
        ptokh, D_IN, pwch + (size_t)3072 * D_IN, D_IN, pbc + 3072,
        nullptr, pvallh, 3072, D_IN);

    mask6_kernel<<<dim3(T / 256, LQ, NB), 256>>>(rel_bias, mask_scale, pw6);
    bcast_latents<<<(BL * D) / 256, 256>>>(latents, plat);

    for (int i = 0; i < NB; i++) {
        // ---- cross attention ----
        ln_half<<<BL, 256>>>(plat, lnx_g + i * D, lnx_b + i * D, ptmph);
        gemm_h16<0><<<dim3(D / 128, BL / 64), 256, GSMH>>>(
            ptmph, D, pwxqkvh + (size_t)i * 3 * D * D, D,
            xb_qkv + (size_t)i * 3 * D, nullptr, pqh, D, D);
        fattn<<<dim3(LQ / BQ, B * H), 256, FA_SMEM>>>(
            pqh, D,
            pkallh + (size_t)i * 512, 3072,
            pvallh + (size_t)i * 512, 3072,
            pw6 + (size_t)i * LQ * T, path, T);
        gemm_h16<2><<<dim3(D / 128, BL / 64), 256, GSMH>>>(
            path, D, pwxoh + (size_t)i * D * D, D, xb_o + i * D,
            plat, nullptr, D, D);

        // ---- cross MLP (pre-LN reuses lnx params) ----
        ln_half<<<BL, 256>>>(plat, lnx_g + i * D, lnx_b + i * D, ptmph);
        gemm_h16<1><<<dim3(HID / 128, BL / 64), 256, GSMH>>>(
            ptmph, D, pwmx1h + (size_t)i * HID * D, D, mx_b1 + i * HID,
            nullptr, phidh, HID, D);
        gemm_h16<2><<<dim3(D / 128, BL / 64), 256, GSMH>>>(
            phidh, HID, pwmx2h + (size_t)i * D * HID, HID, mx_b2 + i * D,
            plat, nullptr, D, HID);

        // ---- self attention ----
        ln_half<<<BL, 256>>>(plat, lns_g + i * D, lns_b + i * D, ptmph);
        gemm_h16<0><<<dim3((3 * D) / 128, BL / 64), 256, GSMH>>>(
            ptmph, D, pwsqkvh + (size_t)i * 3 * D * D, D,
            sb_qkv + (size_t)i * 3 * D, nullptr, psqh, 3 * D, D);
        fattn<<<dim3(LQ / BQ, B * H), 256, FA_SMEM>>>(
            psqh, 3 * D,
            psqh + D, 3 * D,
            psqh + 2 * D, 3 * D,
            nullptr, path, LQ);
        gemm_h16<2><<<dim3(D / 128, BL / 64), 256, GSMH>>>(
            path, D, pwsoh + (size_t)i * D * D, D, sb_o + i * D,
            plat, nullptr, D, D);

        // ---- self MLP ----
        ln_half<<<BL, 256>>>(plat, lns_g + i * D, lns_b + i * D, ptmph);
        gemm_h16<1><<<dim3(HID / 128, BL / 64), 256, GSMH>>>(
            ptmph, D, pwms1h + (size_t)i * HID * D, D, ms_b1 + i * HID,
            nullptr, phidh, HID, D);
        gemm_h16<2><<<dim3(D / 128, BL / 64), 256, GSMH>>>(
            phidh, HID, pwms2h + (size_t)i * D * HID, HID, ms_b2 + i * D,
            plat, nullptr, D, HID);
    }

    // final LN + mean over latents
    ln_kernel<<<BL, 256>>>(plat, lno_g, lno_b, ptmpf);
    mean_kernel<<<(B * D) / 256, 256>>>(ptmpf, out);
}